// round 13
// baseline (speedup 1.0000x reference)
#include <cuda_runtime.h>
#include <cuda_fp16.h>
#include <cstdint>

#define NN 100000
#define EE 1600000
#define HH 128
#define GG 256
#define CC 16
#define KK 2

#define SCAN_BLOCKS ((NN + 255) / 256)   // 391
#define GEMM_BLOCKS ((NN + 127) / 128)   // 782
#define NBLK 256                         // persistent kernel blocks (<=296 resident)
#define MONO_WARPS (NBLK * 8)
#define MONO_CHUNK ((NN + MONO_WARPS - 1) / MONO_WARPS)   // 49

// ---------------- device scratch (static, allowed) ----------------
__device__ __half g_xs16[(size_t)NN * HH];
__device__ __half g_h16 [(size_t)NN * HH];
__device__ float g_dis[NN];
__device__ int   g_deg[NN];
__device__ int   g_rowptr[NN + 1];
__device__ int   g_cursor[NN];
__device__ int   g_csrc[EE];
__device__ float g_stats[2 * HH];
__device__ float g_pool[GG * HH];
__device__ int   g_i64;
__device__ int   g_blk[SCAN_BLOCKS + 8];
__device__ int   g_blkoff[SCAN_BLOCKS + 8];
__device__ __half g_wh[HH * HH];           // W'^T hi fp16 [n][k]
__device__ __half g_wl[HH * HH];           // W'^T lo fp16 residual [n][k]
__device__ float g_wr[HH];
__device__ volatile unsigned g_gen;        // grid-barrier generation
__device__ unsigned g_cnt2;                // grid-barrier arrival count

__device__ __forceinline__ void gsync(unsigned nblk) {
    __syncthreads();
    if (threadIdx.x == 0) {
        __threadfence();
        unsigned gen = g_gen;
        if (atomicAdd(&g_cnt2, 1u) == nblk - 1u) {
            g_cnt2 = 0u;
            __threadfence();
            g_gen = gen + 1u;
        } else {
            while (g_gen == gen) __nanosleep(32);
        }
        __threadfence();
    }
    __syncthreads();
}

__device__ __forceinline__ long long idx_at(const void* p, long long i) {
    if (g_i64) return ((const long long*)p)[i];
    return (long long)((const int*)p)[i];
}

__device__ __forceinline__ void mma_f16(float* c, const uint32_t* a,
                                        uint32_t b0, uint32_t b1) {
    asm volatile(
        "mma.sync.aligned.m16n8k16.row.col.f32.f16.f16.f32 "
        "{%0,%1,%2,%3}, {%4,%5,%6,%7}, {%8,%9}, {%0,%1,%2,%3};\n"
        : "+f"(c[0]), "+f"(c[1]), "+f"(c[2]), "+f"(c[3])
        : "r"(a[0]), "r"(a[1]), "r"(a[2]), "r"(a[3]), "r"(b0), "r"(b1));
}

__device__ __forceinline__ void ldsm4(uint32_t& r0, uint32_t& r1,
                                      uint32_t& r2, uint32_t& r3, uint32_t addr) {
    asm volatile("ldmatrix.sync.aligned.m8n8.x4.shared.b16 {%0,%1,%2,%3}, [%4];"
                 : "=r"(r0), "=r"(r1), "=r"(r2), "=r"(r3) : "r"(addr));
}

__device__ __forceinline__ uint32_t pack2(float a, float b) {
    __half2 h = __floats2half2_rn(a, b);
    return *(uint32_t*)&h;
}

__device__ __forceinline__ void cpa16(uint32_t dst, const void* src, bool pred) {
    asm volatile("cp.async.cg.shared.global [%0], [%1], 16, %2;\n"
                 :: "r"(dst), "l"(src), "r"(pred ? 16 : 0));
}
__device__ __forceinline__ void cpa_commit() {
    asm volatile("cp.async.commit_group;\n");
}
template<int N>
__device__ __forceinline__ void cpa_wait() {
    asm volatile("cp.async.wait_group %0;\n" :: "n"(N));
}

// ====== k_pre: init + W1 prep + hist + scan (single wave, 391 blocks) ======
__global__ void __launch_bounds__(256) k_pre(const int* ei32, const void* ei,
                                             const float* __restrict__ W1) {
    int tid = threadIdx.x, b = blockIdx.x;
    int i = b * 256 + tid;
    // phase A: zero + detect + W1 prep
    if (b == 0 && tid < 32) {
        int lane = tid;
        int v = ei32[2 * lane + 1] | ei32[2 * (lane + 32) + 1] |
                ei32[2 * (lane + 64) + 1] | ei32[2 * (lane + 96) + 1];
        unsigned m = __ballot_sync(0xffffffffu, v != 0);
        if (lane == 0) g_i64 = (m == 0) ? 1 : 0;
    }
    if (i < NN) g_deg[i] = 0;
    if (i < GG * HH) g_pool[i] = 0.f;
    if (i < 2 * HH) g_stats[i] = 0.f;
    if (b == 1 && tid < HH) g_wr[tid] = 0.f;
    if (b < 64) {
        int idx = b * 256 + tid;                    // [0, 16384)
        int k = idx >> 7, n = idx & 127;
        float v = W1[idx];
        __half h = __float2half_rn(v);
        g_wh[n * HH + k] = h;
        g_wl[n * HH + k] = __float2half_rn(v - __half2float(h));
    }
    gsync(SCAN_BLOCKS);
    // phase B: histogram
    for (long long e = (long long)b * 256 + tid; e < EE;
         e += (long long)SCAN_BLOCKS * 256) {
        int d = (int)idx_at(ei, (long long)EE + e);
        atomicAdd(&g_deg[d], 1);
    }
    gsync(SCAN_BLOCKS);
    // phase C: scan (local)
    int v = (i < NN) ? g_deg[i] : 0;
    float dis = rsqrtf((float)v + 1.0f);
    int x = v;
#pragma unroll
    for (int o = 1; o < 32; o <<= 1) {
        int y = __shfl_up_sync(0xffffffffu, x, o);
        if ((tid & 31) >= o) x += y;
    }
    __shared__ int ws[8];
    if ((tid & 31) == 31) ws[tid >> 5] = x;
    __syncthreads();
    if (tid < 8) {
        int s = ws[tid];
#pragma unroll
        for (int o = 1; o < 8; o <<= 1) {
            int y = __shfl_up_sync(0xffu, s, o);
            if (tid >= o) s += y;
        }
        ws[tid] = s;
    }
    __syncthreads();
    int warpoff = (tid >= 32) ? ws[(tid >> 5) - 1] : 0;
    if (tid == 0) g_blk[b] = ws[7];
    gsync(SCAN_BLOCKS);
    if (b == 0) {
        __shared__ int s[256];
        int i0 = 2 * tid, i1 = 2 * tid + 1;
        int v0 = (i0 < SCAN_BLOCKS) ? g_blk[i0] : 0;
        int v1 = (i1 < SCAN_BLOCKS) ? g_blk[i1] : 0;
        int p = v0 + v1;
        s[tid] = p;
        __syncthreads();
        for (int d = 1; d < 256; d <<= 1) {
            int xx = (tid >= d) ? s[tid - d] : 0;
            __syncthreads();
            s[tid] += xx;
            __syncthreads();
        }
        int excl = s[tid] - p;
        if (i0 < SCAN_BLOCKS) g_blkoff[i0] = excl;
        if (i1 < SCAN_BLOCKS) g_blkoff[i1] = excl + v0;
        if (tid == 255) g_rowptr[NN] = s[255];
    }
    gsync(SCAN_BLOCKS);
    int excl = x - v + warpoff + g_blkoff[b];
    if (i < NN) {
        g_rowptr[i] = excl;
        g_cursor[i] = excl;
        g_dis[i] = dis;
    }
}

// ---------------- GEMM body ----------------
#define ST 20
#define TS (128 * ST)
#define SW_H0 TS
#define SW_L0 (2 * TS)
#define BUFS (3 * TS)
#define SMEM_U32 (2 * BUFS)          // 60 KB (MODE0 uses first 3*TS only)

template<int MODE>
__device__ void gemm_body(uint32_t* sm, const float* __restrict__ Ain, int rbase) {
    int tid = threadIdx.x;
    int wid = tid >> 5, lane = tid & 31;
    int wm = wid >> 1, wn = wid & 1;
    uint32_t sbase = (uint32_t)__cvta_generic_to_shared((void*)sm);

    int asub = lane >> 3, ai = lane & 7;
    int a_row = (asub & 1) * 8 + ai;
    int a_k4  = (asub >> 1) * 4;
    int aoff0 = (wm * 32 + a_row) * ST + a_k4;
    int aoff1 = (wm * 32 + 16 + a_row) * ST + a_k4;
    int bsel = lane >> 4;
    int brow = lane & 7;
    int b_k4 = ((lane >> 3) & 1) * 4;
    int boff = (wn * 64 + brow) * ST + b_k4;

    float acc[2][8][4];
#pragma unroll
    for (int mt = 0; mt < 2; mt++)
#pragma unroll
        for (int j = 0; j < 8; j++)
#pragma unroll
            for (int q = 0; q < 4; q++) acc[mt][j][q] = 0.f;

    if (MODE == 0) {
        int btile = boff + (bsel ? SW_L0 : SW_H0);
        for (int ch = 0; ch < 4; ch++) {
            int kbase = ch * 32;
#pragma unroll
            for (int i = 0; i < 2; i++) {
                int idx = i * 256 + tid;
                int m = idx >> 2, q = idx & 3;
                int gr = rbase + m;
                float4 v0 = make_float4(0.f, 0.f, 0.f, 0.f);
                float4 v1 = make_float4(0.f, 0.f, 0.f, 0.f);
                if (gr < NN) {
                    v0 = *(const float4*)&Ain[(size_t)gr * HH + kbase + 8 * q];
                    v1 = *(const float4*)&Ain[(size_t)gr * HH + kbase + 8 * q + 4];
                }
                *(uint4*)&sm[m * ST + 4 * q] = make_uint4(
                    pack2(v0.x, v0.y), pack2(v0.z, v0.w),
                    pack2(v1.x, v1.y), pack2(v1.z, v1.w));
            }
#pragma unroll
            for (int i = 0; i < 2; i++) {
                int idx = i * 256 + tid;
                int n = idx >> 2, q = idx & 3;
                *(uint4*)&sm[SW_H0 + n * ST + 4 * q] =
                    *(const uint4*)&g_wh[n * HH + kbase + 8 * q];
                *(uint4*)&sm[SW_L0 + n * ST + 4 * q] =
                    *(const uint4*)&g_wl[n * HH + kbase + 8 * q];
            }
            __syncthreads();
#pragma unroll
            for (int ks = 0; ks < 2; ks++) {
                int koff = ks * 8;
                uint32_t ah[2][4];
                ldsm4(ah[0][0], ah[0][1], ah[0][2], ah[0][3],
                      sbase + 4 * (aoff0 + koff));
                ldsm4(ah[1][0], ah[1][1], ah[1][2], ah[1][3],
                      sbase + 4 * (aoff1 + koff));
#pragma unroll
                for (int j = 0; j < 8; j++) {
                    uint32_t bh0, bh1, bl0, bl1;
                    ldsm4(bh0, bh1, bl0, bl1,
                          sbase + 4 * (btile + j * 8 * ST + koff));
#pragma unroll
                    for (int mt = 0; mt < 2; mt++) {
                        mma_f16(acc[mt][j], ah[mt], bh0, bh1);
                        mma_f16(acc[mt][j], ah[mt], bl0, bl1);
                    }
                }
            }
            __syncthreads();
        }
    } else {
        int btile = boff + TS + bsel * TS;
        int m_ = tid >> 2, q_ = tid & 3;
        int m2 = (256 + tid) >> 2, q2 = (256 + tid) & 3;
#define ISSUE_CHUNK(CH, BUF) { \
        int kb = (CH) * 32; int bo = (BUF) * BUFS; \
        { int gr = rbase + m_; bool p = gr < NN; \
          const __half* s = p ? &g_h16[(size_t)gr * HH + kb + 8 * q_] : &g_h16[0]; \
          cpa16(sbase + 4 * (bo + m_ * ST + 4 * q_), s, p); } \
        { int gr = rbase + m2; bool p = gr < NN; \
          const __half* s = p ? &g_h16[(size_t)gr * HH + kb + 8 * q2] : &g_h16[0]; \
          cpa16(sbase + 4 * (bo + m2 * ST + 4 * q2), s, p); } \
        cpa16(sbase + 4 * (bo + TS + m_ * ST + 4 * q_),      &g_wh[m_ * HH + kb + 8 * q_], true); \
        cpa16(sbase + 4 * (bo + TS + m2 * ST + 4 * q2),      &g_wh[m2 * HH + kb + 8 * q2], true); \
        cpa16(sbase + 4 * (bo + 2 * TS + m_ * ST + 4 * q_),  &g_wl[m_ * HH + kb + 8 * q_], true); \
        cpa16(sbase + 4 * (bo + 2 * TS + m2 * ST + 4 * q2),  &g_wl[m2 * HH + kb + 8 * q2], true); \
        cpa_commit(); }

        ISSUE_CHUNK(0, 0);
#pragma unroll
        for (int ch = 0; ch < 4; ch++) {
            int buf = ch & 1;
            if (ch < 3) { ISSUE_CHUNK(ch + 1, buf ^ 1); cpa_wait<1>(); }
            else cpa_wait<0>();
            __syncthreads();
            int bo = buf * BUFS;
#pragma unroll
            for (int ks = 0; ks < 2; ks++) {
                int koff = ks * 8;
                uint32_t ah[2][4];
                ldsm4(ah[0][0], ah[0][1], ah[0][2], ah[0][3],
                      sbase + 4 * (bo + aoff0 + koff));
                ldsm4(ah[1][0], ah[1][1], ah[1][2], ah[1][3],
                      sbase + 4 * (bo + aoff1 + koff));
#pragma unroll
                for (int j = 0; j < 8; j++) {
                    uint32_t bh0, bh1, bl0, bl1;
                    ldsm4(bh0, bh1, bl0, bl1,
                          sbase + 4 * (bo + btile + j * 8 * ST + koff));
#pragma unroll
                    for (int mt = 0; mt < 2; mt++) {
                        mma_f16(acc[mt][j], ah[mt], bh0, bh1);
                        mma_f16(acc[mt][j], ah[mt], bl0, bl1);
                    }
                }
            }
            __syncthreads();
        }
#undef ISSUE_CHUNK
    }

    int ly = lane >> 2, lx = lane & 3;
#pragma unroll
    for (int mt = 0; mt < 2; mt++) {
        int r0 = rbase + wm * 32 + mt * 16 + ly;
        int r1 = r0 + 8;
        float d0 = (r0 < NN) ? g_dis[r0] : 0.f;
        float d1 = (r1 < NN) ? g_dis[r1] : 0.f;
#pragma unroll
        for (int j = 0; j < 8; j++) {
            int cb = wn * 64 + 8 * j + 2 * lx;
            float ra = g_wr[cb], rb = g_wr[cb + 1];
            if (r0 < NN) {
                __half2 o = __floats2half2_rn(d0 * (acc[mt][j][0] + ra),
                                              d0 * (acc[mt][j][1] + rb));
                *(__half2*)&g_xs16[(size_t)r0 * HH + cb] = o;
            }
            if (r1 < NN) {
                __half2 o = __floats2half2_rn(d1 * (acc[mt][j][2] + ra),
                                              d1 * (acc[mt][j][3] + rb));
                *(__half2*)&g_xs16[(size_t)r1 * HH + cb] = o;
            }
        }
    }
}

// ---------------- agg phase (device) ----------------
#define ACCS(u0, u1, X, Y, Z, W) { \
    float2 t0 = __half22float2(*(__half2*)&(u0)); \
    float2 t1 = __half22float2(*(__half2*)&(u1)); \
    X += t0.x; Y += t0.y; Z += t1.x; W += t1.y; }

template<bool LAST>
__device__ void agg_phase(const float* __restrict__ bias,
                          const void* __restrict__ batch) {
    int tid = threadIdx.x;
    int wid = tid >> 5, lane = tid & 31;
    float4 b4 = ((const float4*)bias)[lane];
    float s0 = 0.f, s1 = 0.f, s2 = 0.f, s3 = 0.f;
    float q0 = 0.f, q1 = 0.f, q2 = 0.f, q3 = 0.f;
    const uint2* xsv = (const uint2*)g_xs16;

    int wgl = blockIdx.x * 8 + wid;
    int istart = wgl * MONO_CHUNK;
    int iend = istart + MONO_CHUNK;
    if (iend > NN) iend = NN;

    int curg = -1;
    float px = 0.f, py = 0.f, pz = 0.f, pw = 0.f;

    for (int i = istart; i < iend; i++) {
        uint2 u = xsv[(long long)i * 32 + lane];
        float ax0, ay0, az0, aw0;
        float ax1 = 0.f, ay1 = 0.f, az1 = 0.f, aw1 = 0.f;
        {
            float2 a0 = __half22float2(*(__half2*)&u.x);
            float2 a1 = __half22float2(*(__half2*)&u.y);
            ax0 = a0.x; ay0 = a0.y; az0 = a1.x; aw0 = a1.y;
        }
        int e0 = g_rowptr[i], e1 = g_rowptr[i + 1];
        int e = e0;
        for (; e + 4 <= e1; e += 4) {
            int sA = g_csrc[e], sB = g_csrc[e + 1];
            int sC = g_csrc[e + 2], sD = g_csrc[e + 3];
            uint2 vA = xsv[(long long)sA * 32 + lane];
            uint2 vB = xsv[(long long)sB * 32 + lane];
            uint2 vC = xsv[(long long)sC * 32 + lane];
            uint2 vD = xsv[(long long)sD * 32 + lane];
            ACCS(vA.x, vA.y, ax0, ay0, az0, aw0);
            ACCS(vB.x, vB.y, ax1, ay1, az1, aw1);
            ACCS(vC.x, vC.y, ax0, ay0, az0, aw0);
            ACCS(vD.x, vD.y, ax1, ay1, az1, aw1);
        }
        for (; e < e1; e++) {
            int s = g_csrc[e];
            uint2 v = xsv[(long long)s * 32 + lane];
            ACCS(v.x, v.y, ax0, ay0, az0, aw0);
        }
        float acx = ax0 + ax1, acy = ay0 + ay1;
        float acz = az0 + az1, acw = aw0 + aw1;
        float d = g_dis[i];
        float yx = fmaxf(fmaf(d, acx, b4.x), 0.f);
        float yy = fmaxf(fmaf(d, acy, b4.y), 0.f);
        float yz = fmaxf(fmaf(d, acz, b4.z), 0.f);
        float yw = fmaxf(fmaf(d, acw, b4.w), 0.f);
        if (!LAST) {
            uint2 o;
            *(__half2*)&o.x = __floats2half2_rn(yx, yy);
            *(__half2*)&o.y = __floats2half2_rn(yz, yw);
            ((uint2*)g_h16)[(long long)i * 32 + lane] = o;
        } else {
            int g = (int)idx_at(batch, i);
            if (g != curg) {
                if (curg >= 0) {
                    float* p = &g_pool[curg * HH + lane * 4];
                    atomicAdd(p + 0, px); atomicAdd(p + 1, py);
                    atomicAdd(p + 2, pz); atomicAdd(p + 3, pw);
                }
                curg = g; px = py = pz = pw = 0.f;
            }
            px += yx; py += yy; pz += yz; pw += yw;
        }
        s0 += yx; s1 += yy; s2 += yz; s3 += yw;
        q0 += yx * yx; q1 += yy * yy; q2 += yz * yz; q3 += yw * yw;
    }
    if (LAST && curg >= 0) {
        float* p = &g_pool[curg * HH + lane * 4];
        atomicAdd(p + 0, px); atomicAdd(p + 1, py);
        atomicAdd(p + 2, pz); atomicAdd(p + 3, pw);
    }
    __shared__ float red[2 * HH];
    red[tid] = 0.f;
    __syncthreads();
    atomicAdd(&red[lane * 4 + 0], s0);
    atomicAdd(&red[lane * 4 + 1], s1);
    atomicAdd(&red[lane * 4 + 2], s2);
    atomicAdd(&red[lane * 4 + 3], s3);
    atomicAdd(&red[HH + lane * 4 + 0], q0);
    atomicAdd(&red[HH + lane * 4 + 1], q1);
    atomicAdd(&red[HH + lane * 4 + 2], q2);
    atomicAdd(&red[HH + lane * 4 + 3], q3);
    __syncthreads();
    atomicAdd(&g_stats[tid], red[tid]);
}

// ---------------- prep phase: fold BN affine (from stats) into W ----------------
__device__ void prep_phase(const float* __restrict__ W,
                           const float* __restrict__ gamma,
                           const float* __restrict__ beta) {
    int tid = threadIdx.x;
    if (blockIdx.x < 64) {
        int idx = blockIdx.x * 256 + tid;
        int k = idx >> 7, n = idx & 127;
        float m = g_stats[k] * (1.0f / NN);
        float var = fmaxf(g_stats[HH + k] * (1.0f / NN) - m * m, 0.f);
        float s = gamma[k] * rsqrtf(var + 1e-5f);
        float v = W[idx] * s;
        __half h = __float2half_rn(v);
        g_wh[n * HH + k] = h;
        g_wl[n * HH + k] = __float2half_rn(v - __half2float(h));
    } else if (blockIdx.x == 64) {
        __shared__ float ts[HH];
        if (tid < HH) {
            float m = g_stats[tid] * (1.0f / NN);
            float var = fmaxf(g_stats[HH + tid] * (1.0f / NN) - m * m, 0.f);
            float s = gamma[tid] * rsqrtf(var + 1e-5f);
            ts[tid] = beta[tid] - m * s;
        }
        __syncthreads();
        if (tid < HH) {
            float r = 0.f;
#pragma unroll 4
            for (int k = 0; k < HH; k++) r = fmaf(ts[k], W[k * HH + tid], r);
            g_wr[tid] = r;
        }
    }
}

__device__ __forceinline__ int lb_batch(const void* batch, int val) {
    int lo = 0, hi = NN;
    while (lo < hi) {
        int mid = (lo + hi) >> 1;
        if ((int)idx_at(batch, mid) < val) lo = mid + 1;
        else hi = mid;
    }
    return lo;
}

// ====== k_mono: place -> (gemm, agg, prep) x3 -> final, one persistent kernel ======
__global__ void __launch_bounds__(256, 2) k_mono(
    const void* ei, const void* batch, const float* __restrict__ x,
    const float* b1, const float* b2, const float* b3,
    const float* g1, const float* be1, const float* g2, const float* be2,
    const float* g3, const float* be3,
    const float* W2, const float* W3,
    const float* clinical, const float* Wc, const float* bc,
    float* __restrict__ out)
{
    extern __shared__ uint32_t sm[];
    int tid = threadIdx.x;

    // phase: CSR place
    for (long long e = (long long)blockIdx.x * 256 + tid; e < EE;
         e += (long long)NBLK * 256) {
        int d = (int)idx_at(ei, (long long)EE + e);
        int pos = atomicAdd(&g_cursor[d], 1);
        g_csrc[pos] = (int)idx_at(ei, e);
    }
    gsync(NBLK);

    // layer 1
    for (int t = blockIdx.x; t < GEMM_BLOCKS; t += NBLK) gemm_body<0>(sm, x, t * 128);
    gsync(NBLK);
    agg_phase<false>(b1, batch);
    gsync(NBLK);
    prep_phase(W2, g1, be1);
    gsync(NBLK);

    // layer 2 (zero stats of layer 1 during gemm phase)
    if (blockIdx.x == NBLK - 1 && tid < 2 * HH) g_stats[tid] = 0.f;
    for (int t = blockIdx.x; t < GEMM_BLOCKS; t += NBLK) gemm_body<1>(sm, nullptr, t * 128);
    gsync(NBLK);
    agg_phase<false>(b2, batch);
    gsync(NBLK);
    prep_phase(W3, g2, be2);
    gsync(NBLK);

    // layer 3
    if (blockIdx.x == NBLK - 1 && tid < 2 * HH) g_stats[tid] = 0.f;
    for (int t = blockIdx.x; t < GEMM_BLOCKS; t += NBLK) gemm_body<1>(sm, nullptr, t * 128);
    gsync(NBLK);
    agg_phase<true>(b3, batch);
    gsync(NBLK);

    // final head (block 0): BN3 affine from stats, pooled mean, linear
    if (blockIdx.x == 0) {
        __shared__ float bs[HH], bt[HH];
        if (tid < HH) {
            float m = g_stats[tid] * (1.0f / NN);
            float var = fmaxf(g_stats[HH + tid] * (1.0f / NN) - m * m, 0.f);
            float s = g3[tid] * rsqrtf(var + 1e-5f);
            bs[tid] = s;
            bt[tid] = be3[tid] - m * s;
        }
        __syncthreads();
        int g = tid;    // 256 threads = GG graphs
        int c = lb_batch(batch, g + 1) - lb_batch(batch, g);
        float cnt = fmaxf((float)c, 1.0f);
        float r0 = bc[0], r1 = bc[1];
#pragma unroll 4
        for (int j = 0; j < HH; j++) {
            float p = g_pool[g * HH + j] / cnt;
            p = fmaf(p, bs[j], bt[j]);
            r0 = fmaf(p, Wc[j * KK + 0], r0);
            r1 = fmaf(p, Wc[j * KK + 1], r1);
        }
#pragma unroll
        for (int j = 0; j < CC; j++) {
            float cl = clinical[g * CC + j];
            r0 = fmaf(cl, Wc[(HH + j) * KK + 0], r0);
            r1 = fmaf(cl, Wc[(HH + j) * KK + 1], r1);
        }
        out[g * KK + 0] = r0;
        out[g * KK + 1] = r1;
    }
}

// ---------------- launch ----------------
extern "C" void kernel_launch(void* const* d_in, const int* in_sizes, int n_in,
                              void* d_out, int out_size) {
    const float* x        = (const float*)d_in[0];
    const void*  ei       = d_in[1];
    const void*  batch    = d_in[2];
    const float* clinical = (const float*)d_in[3];
    const float* W1 = (const float*)d_in[4];  const float* b1 = (const float*)d_in[5];
    const float* W2 = (const float*)d_in[6];  const float* b2 = (const float*)d_in[7];
    const float* W3 = (const float*)d_in[8];  const float* b3 = (const float*)d_in[9];
    const float* g1 = (const float*)d_in[10]; const float* be1 = (const float*)d_in[11];
    const float* g2 = (const float*)d_in[12]; const float* be2 = (const float*)d_in[13];
    const float* g3 = (const float*)d_in[14]; const float* be3 = (const float*)d_in[15];
    const float* Wc = (const float*)d_in[16]; const float* bc = (const float*)d_in[17];
    float* out = (float*)d_out;

    const size_t smem = SMEM_U32 * sizeof(uint32_t);   // 60 KB

    cudaFuncSetAttribute(k_mono,
                         cudaFuncAttributeMaxDynamicSharedMemorySize, (int)smem);

    k_pre<<<SCAN_BLOCKS, 256>>>((const int*)ei, ei, W1);
    k_mono<<<NBLK, 256, smem>>>(ei, batch, x,
                                b1, b2, b3, g1, be1, g2, be2, g3, be3,
                                W2, W3, clinical, Wc, bc, out);
}

// round 14
// speedup vs baseline: 1.1173x; 1.1173x over previous
#include <cuda_runtime.h>
#include <cuda_fp16.h>
#include <cstdint>

#define NN 100000
#define EE 1600000
#define HH 128
#define GG 256
#define CC 16
#define KK 2

#define PRE_BLOCKS ((NN + 255) / 256)    // 391 (single wave, grid-barrier safe)
#define GEMM_BLOCKS ((NN + 127) / 128)   // 782
#define AGG_BLOCKS 1024
#define AGG_WARPS (AGG_BLOCKS * 8)
#define AGG_CHUNK ((NN + AGG_WARPS - 1) / AGG_WARPS)   // 13

// ---------------- device scratch (static, allowed) ----------------
__device__ __half g_xs16[(size_t)NN * HH];
__device__ __half g_h16 [(size_t)NN * HH];
__device__ float g_dis[NN];
__device__ int   g_deg[NN];
__device__ int   g_rowptr[NN + 1];
__device__ int   g_cursor[NN];
__device__ int   g_csrc[EE];
__device__ float g_stats[2 * HH];
__device__ float g_bns[HH];
__device__ float g_bnt[HH];
__device__ float g_pool[GG * HH];
__device__ int   g_i64;
__device__ int   g_blk[PRE_BLOCKS + 8];
__device__ int   g_blkoff[PRE_BLOCKS + 8];
__device__ __half g_wh[HH * HH];           // W'^T hi fp16 [n][k]
__device__ __half g_wl[HH * HH];           // W'^T lo fp16 residual [n][k]
__device__ float g_wr[HH];
__device__ unsigned g_arr;                 // agg last-block counter
__device__ volatile unsigned g_gen;        // generation grid barrier
__device__ unsigned g_gcnt;

__device__ __forceinline__ void gsync(unsigned nblk) {
    __syncthreads();
    if (threadIdx.x == 0) {
        __threadfence();
        unsigned gen = g_gen;
        if (atomicAdd(&g_gcnt, 1u) == nblk - 1u) {
            g_gcnt = 0u;
            __threadfence();
            g_gen = gen + 1u;
        } else {
            while (g_gen == gen) __nanosleep(32);
        }
        __threadfence();
    }
    __syncthreads();
}

__device__ __forceinline__ long long idx_at(const void* p, long long i) {
    if (g_i64) return ((const long long*)p)[i];
    return (long long)((const int*)p)[i];
}

__device__ __forceinline__ void mma_f16(float* c, const uint32_t* a,
                                        uint32_t b0, uint32_t b1) {
    asm volatile(
        "mma.sync.aligned.m16n8k16.row.col.f32.f16.f16.f32 "
        "{%0,%1,%2,%3}, {%4,%5,%6,%7}, {%8,%9}, {%0,%1,%2,%3};\n"
        : "+f"(c[0]), "+f"(c[1]), "+f"(c[2]), "+f"(c[3])
        : "r"(a[0]), "r"(a[1]), "r"(a[2]), "r"(a[3]), "r"(b0), "r"(b1));
}

__device__ __forceinline__ void ldsm4(uint32_t& r0, uint32_t& r1,
                                      uint32_t& r2, uint32_t& r3, uint32_t addr) {
    asm volatile("ldmatrix.sync.aligned.m8n8.x4.shared.b16 {%0,%1,%2,%3}, [%4];"
                 : "=r"(r0), "=r"(r1), "=r"(r2), "=r"(r3) : "r"(addr));
}

__device__ __forceinline__ uint32_t pack2(float a, float b) {
    __half2 h = __floats2half2_rn(a, b);
    return *(uint32_t*)&h;
}

__device__ __forceinline__ void cpa16(uint32_t dst, const void* src, bool pred) {
    asm volatile("cp.async.cg.shared.global [%0], [%1], 16, %2;\n"
                 :: "r"(dst), "l"(src), "r"(pred ? 16 : 0));
}
__device__ __forceinline__ void cpa_commit() {
    asm volatile("cp.async.commit_group;\n");
}
template<int N>
__device__ __forceinline__ void cpa_wait() {
    asm volatile("cp.async.wait_group %0;\n" :: "n"(N));
}

__device__ __forceinline__ void acc8(const uint4& v, float* a) {
    float2 t;
    t = __half22float2(*(__half2*)&v.x); a[0] += t.x; a[1] += t.y;
    t = __half22float2(*(__half2*)&v.y); a[2] += t.x; a[3] += t.y;
    t = __half22float2(*(__half2*)&v.z); a[4] += t.x; a[5] += t.y;
    t = __half22float2(*(__half2*)&v.w); a[6] += t.x; a[7] += t.y;
}

// ====== launch 1: init (zero + detect + W1 prep) -> barrier -> histogram ======
__global__ void __launch_bounds__(256) k_init_hist(const int* ei32, const void* ei,
                                                   const float* __restrict__ W1) {
    int tid = threadIdx.x, b = blockIdx.x;
    int i = b * 256 + tid;
    if (b == 0 && tid < 32) {
        int lane = tid;
        int v = ei32[2 * lane + 1] | ei32[2 * (lane + 32) + 1] |
                ei32[2 * (lane + 64) + 1] | ei32[2 * (lane + 96) + 1];
        unsigned m = __ballot_sync(0xffffffffu, v != 0);
        if (lane == 0) g_i64 = (m == 0) ? 1 : 0;
    }
    if (i < NN) g_deg[i] = 0;
    if (i < GG * HH) g_pool[i] = 0.f;
    if (i < 2 * HH) g_stats[i] = 0.f;
    if (i == 0) g_arr = 0u;
    if (b == 1 && tid < HH) g_wr[tid] = 0.f;
    if (b < 64) {
        int idx = b * 256 + tid;
        int k = idx >> 7, n = idx & 127;
        float v = W1[idx];
        __half h = __float2half_rn(v);
        g_wh[n * HH + k] = h;
        g_wl[n * HH + k] = __float2half_rn(v - __half2float(h));
    }
    gsync(PRE_BLOCKS);
    for (long long e = (long long)b * 256 + tid; e < EE;
         e += (long long)PRE_BLOCKS * 256) {
        int d = (int)idx_at(ei, (long long)EE + e);
        atomicAdd(&g_deg[d], 1);
    }
}

// ====== launch 2: scan (rowptr/cursor/dis) -> barrier -> CSR place ======
__global__ void __launch_bounds__(256) k_scan_place(const void* ei) {
    int tid = threadIdx.x, b = blockIdx.x;
    int i = b * 256 + tid;
    int v = (i < NN) ? g_deg[i] : 0;
    float dis = rsqrtf((float)v + 1.0f);
    int x = v;
#pragma unroll
    for (int o = 1; o < 32; o <<= 1) {
        int y = __shfl_up_sync(0xffffffffu, x, o);
        if ((tid & 31) >= o) x += y;
    }
    __shared__ int ws[8];
    if ((tid & 31) == 31) ws[tid >> 5] = x;
    __syncthreads();
    if (tid < 8) {
        int s = ws[tid];
#pragma unroll
        for (int o = 1; o < 8; o <<= 1) {
            int y = __shfl_up_sync(0xffu, s, o);
            if (tid >= o) s += y;
        }
        ws[tid] = s;
    }
    __syncthreads();
    int warpoff = (tid >= 32) ? ws[(tid >> 5) - 1] : 0;
    if (tid == 0) g_blk[b] = ws[7];
    gsync(PRE_BLOCKS);
    if (b == 0) {
        __shared__ int s[256];
        int i0 = 2 * tid, i1 = 2 * tid + 1;
        int v0 = (i0 < PRE_BLOCKS) ? g_blk[i0] : 0;
        int v1 = (i1 < PRE_BLOCKS) ? g_blk[i1] : 0;
        int p = v0 + v1;
        s[tid] = p;
        __syncthreads();
        for (int d = 1; d < 256; d <<= 1) {
            int xx = (tid >= d) ? s[tid - d] : 0;
            __syncthreads();
            s[tid] += xx;
            __syncthreads();
        }
        int excl = s[tid] - p;
        if (i0 < PRE_BLOCKS) g_blkoff[i0] = excl;
        if (i1 < PRE_BLOCKS) g_blkoff[i1] = excl + v0;
        if (tid == 255) g_rowptr[NN] = s[255];
    }
    gsync(PRE_BLOCKS);
    int excl = x - v + warpoff + g_blkoff[b];
    if (i < NN) {
        g_rowptr[i] = excl;
        g_cursor[i] = excl;
        g_dis[i] = dis;
    }
    gsync(PRE_BLOCKS);
    for (long long e = (long long)b * 256 + tid; e < EE;
         e += (long long)PRE_BLOCKS * 256) {
        int d = (int)idx_at(ei, (long long)EE + e);
        int pos = atomicAdd(&g_cursor[d], 1);
        g_csrc[pos] = (int)idx_at(ei, e);
    }
}

__global__ void k_prepw_aff_r(const float* __restrict__ W) {
    if (blockIdx.x < 64) {
        int idx = blockIdx.x * 256 + threadIdx.x;
        int k = idx >> 7, n = idx & 127;
        float v = W[idx] * g_bns[k];
        __half h = __float2half_rn(v);
        g_wh[n * HH + k] = h;
        g_wl[n * HH + k] = __float2half_rn(v - __half2float(h));
    } else if (threadIdx.x < HH) {
        int n = threadIdx.x;
        float r = 0.f;
#pragma unroll 4
        for (int k = 0; k < HH; k++) r = fmaf(g_bnt[k], W[k * HH + n], r);
        g_wr[n] = r;
    }
}

// ---------------- fp16 tensor-core GEMM (unchanged from R12) ----------------
#define ST 20
#define TS (128 * ST)
#define SW_H0 TS
#define SW_L0 (2 * TS)
#define SMEM0_U32 (3 * TS)          // 30 KB
#define BUFS (3 * TS)
#define SMEM1_U32 (2 * BUFS)        // 60 KB

template<int MODE>
__global__ void __launch_bounds__(256, 2) k_gemm_tc(const float* __restrict__ Ain) {
    extern __shared__ uint32_t sm[];
    int tid = threadIdx.x;
    int wid = tid >> 5, lane = tid & 31;
    int wm = wid >> 1, wn = wid & 1;
    int rbase = blockIdx.x * 128;
    uint32_t sbase = (uint32_t)__cvta_generic_to_shared((void*)sm);

    int asub = lane >> 3, ai = lane & 7;
    int a_row = (asub & 1) * 8 + ai;
    int a_k4  = (asub >> 1) * 4;
    int aoff0 = (wm * 32 + a_row) * ST + a_k4;
    int aoff1 = (wm * 32 + 16 + a_row) * ST + a_k4;
    int bsel = lane >> 4;
    int brow = lane & 7;
    int b_k4 = ((lane >> 3) & 1) * 4;
    int boff = (wn * 64 + brow) * ST + b_k4;

    float acc[2][8][4];
#pragma unroll
    for (int mt = 0; mt < 2; mt++)
#pragma unroll
        for (int j = 0; j < 8; j++)
#pragma unroll
            for (int q = 0; q < 4; q++) acc[mt][j][q] = 0.f;

    if (MODE == 0) {
        int btile = boff + (bsel ? SW_L0 : SW_H0);
        for (int ch = 0; ch < 4; ch++) {
            int kbase = ch * 32;
#pragma unroll
            for (int i = 0; i < 2; i++) {
                int idx = i * 256 + tid;
                int m = idx >> 2, q = idx & 3;
                int gr = rbase + m;
                float4 v0 = make_float4(0.f, 0.f, 0.f, 0.f);
                float4 v1 = make_float4(0.f, 0.f, 0.f, 0.f);
                if (gr < NN) {
                    v0 = *(const float4*)&Ain[(size_t)gr * HH + kbase + 8 * q];
                    v1 = *(const float4*)&Ain[(size_t)gr * HH + kbase + 8 * q + 4];
                }
                *(uint4*)&sm[m * ST + 4 * q] = make_uint4(
                    pack2(v0.x, v0.y), pack2(v0.z, v0.w),
                    pack2(v1.x, v1.y), pack2(v1.z, v1.w));
            }
#pragma unroll
            for (int i = 0; i < 2; i++) {
                int idx = i * 256 + tid;
                int n = idx >> 2, q = idx & 3;
                *(uint4*)&sm[SW_H0 + n * ST + 4 * q] =
                    *(const uint4*)&g_wh[n * HH + kbase + 8 * q];
                *(uint4*)&sm[SW_L0 + n * ST + 4 * q] =
                    *(const uint4*)&g_wl[n * HH + kbase + 8 * q];
            }
            __syncthreads();
#pragma unroll
            for (int ks = 0; ks < 2; ks++) {
                int koff = ks * 8;
                uint32_t ah[2][4];
                ldsm4(ah[0][0], ah[0][1], ah[0][2], ah[0][3],
                      sbase + 4 * (aoff0 + koff));
                ldsm4(ah[1][0], ah[1][1], ah[1][2], ah[1][3],
                      sbase + 4 * (aoff1 + koff));
#pragma unroll
                for (int j = 0; j < 8; j++) {
                    uint32_t bh0, bh1, bl0, bl1;
                    ldsm4(bh0, bh1, bl0, bl1,
                          sbase + 4 * (btile + j * 8 * ST + koff));
#pragma unroll
                    for (int mt = 0; mt < 2; mt++) {
                        mma_f16(acc[mt][j], ah[mt], bh0, bh1);
                        mma_f16(acc[mt][j], ah[mt], bl0, bl1);
                    }
                }
            }
            __syncthreads();
        }
    } else {
        int btile = boff + TS + bsel * TS;
        int m_ = tid >> 2, q_ = tid & 3;
        int m2 = (256 + tid) >> 2, q2 = (256 + tid) & 3;
#define ISSUE_CHUNK(CH, BUF) { \
        int kb = (CH) * 32; int bo = (BUF) * BUFS; \
        { int gr = rbase + m_; bool p = gr < NN; \
          const __half* s = p ? &g_h16[(size_t)gr * HH + kb + 8 * q_] : &g_h16[0]; \
          cpa16(sbase + 4 * (bo + m_ * ST + 4 * q_), s, p); } \
        { int gr = rbase + m2; bool p = gr < NN; \
          const __half* s = p ? &g_h16[(size_t)gr * HH + kb + 8 * q2] : &g_h16[0]; \
          cpa16(sbase + 4 * (bo + m2 * ST + 4 * q2), s, p); } \
        cpa16(sbase + 4 * (bo + TS + m_ * ST + 4 * q_),      &g_wh[m_ * HH + kb + 8 * q_], true); \
        cpa16(sbase + 4 * (bo + TS + m2 * ST + 4 * q2),      &g_wh[m2 * HH + kb + 8 * q2], true); \
        cpa16(sbase + 4 * (bo + 2 * TS + m_ * ST + 4 * q_),  &g_wl[m_ * HH + kb + 8 * q_], true); \
        cpa16(sbase + 4 * (bo + 2 * TS + m2 * ST + 4 * q2),  &g_wl[m2 * HH + kb + 8 * q2], true); \
        cpa_commit(); }

        ISSUE_CHUNK(0, 0);
#pragma unroll
        for (int ch = 0; ch < 4; ch++) {
            int buf = ch & 1;
            if (ch < 3) { ISSUE_CHUNK(ch + 1, buf ^ 1); cpa_wait<1>(); }
            else cpa_wait<0>();
            __syncthreads();
            int bo = buf * BUFS;
#pragma unroll
            for (int ks = 0; ks < 2; ks++) {
                int koff = ks * 8;
                uint32_t ah[2][4];
                ldsm4(ah[0][0], ah[0][1], ah[0][2], ah[0][3],
                      sbase + 4 * (bo + aoff0 + koff));
                ldsm4(ah[1][0], ah[1][1], ah[1][2], ah[1][3],
                      sbase + 4 * (bo + aoff1 + koff));
#pragma unroll
                for (int j = 0; j < 8; j++) {
                    uint32_t bh0, bh1, bl0, bl1;
                    ldsm4(bh0, bh1, bl0, bl1,
                          sbase + 4 * (bo + btile + j * 8 * ST + koff));
#pragma unroll
                    for (int mt = 0; mt < 2; mt++) {
                        mma_f16(acc[mt][j], ah[mt], bh0, bh1);
                        mma_f16(acc[mt][j], ah[mt], bl0, bl1);
                    }
                }
            }
            __syncthreads();
        }
#undef ISSUE_CHUNK
    }

    int ly = lane >> 2, lx = lane & 3;
#pragma unroll
    for (int mt = 0; mt < 2; mt++) {
        int r0 = rbase + wm * 32 + mt * 16 + ly;
        int r1 = r0 + 8;
        float d0 = (r0 < NN) ? g_dis[r0] : 0.f;
        float d1 = (r1 < NN) ? g_dis[r1] : 0.f;
#pragma unroll
        for (int j = 0; j < 8; j++) {
            int cb = wn * 64 + 8 * j + 2 * lx;
            float ra = g_wr[cb], rb = g_wr[cb + 1];
            if (r0 < NN) {
                __half2 o = __floats2half2_rn(d0 * (acc[mt][j][0] + ra),
                                              d0 * (acc[mt][j][1] + rb));
                *(__half2*)&g_xs16[(size_t)r0 * HH + cb] = o;
            }
            if (r1 < NN) {
                __half2 o = __floats2half2_rn(d1 * (acc[mt][j][2] + ra),
                                              d1 * (acc[mt][j][3] + rb));
                *(__half2*)&g_xs16[(size_t)r1 * HH + cb] = o;
            }
        }
    }
}

// ------- aggregation: 16-lane uint4 gathers, 2 edges per warp-iteration -------
__device__ __forceinline__ int lb_batch(const void* batch, int val) {
    int lo = 0, hi = NN;
    while (lo < hi) {
        int mid = (lo + hi) >> 1;
        if ((int)idx_at(batch, mid) < val) lo = mid + 1;
        else hi = mid;
    }
    return lo;
}

template<bool LAST>
__global__ void __launch_bounds__(256) k_agg(const float* __restrict__ bias,
                                             const void* __restrict__ batch,
                                             const float* __restrict__ gamma,
                                             const float* __restrict__ beta,
                                             const float* __restrict__ clinical,
                                             const float* __restrict__ Wc,
                                             const float* __restrict__ bc,
                                             float* __restrict__ out) {
    int tid = threadIdx.x;
    int wid = tid >> 5, lane = tid & 31;
    int li = lane & 15, half = lane >> 4;
    const uint4* xs4 = (const uint4*)g_xs16;

    // per-lane bias for features [8li, 8li+8)
    float bl[8];
    {
        float4 f0 = ((const float4*)bias)[li * 2];
        float4 f1 = ((const float4*)bias)[li * 2 + 1];
        bl[0] = f0.x; bl[1] = f0.y; bl[2] = f0.z; bl[3] = f0.w;
        bl[4] = f1.x; bl[5] = f1.y; bl[6] = f1.z; bl[7] = f1.w;
    }
    float st[8], qt[8];
#pragma unroll
    for (int j = 0; j < 8; j++) { st[j] = 0.f; qt[j] = 0.f; }

    int wgl = blockIdx.x * 8 + wid;
    int istart = wgl * AGG_CHUNK;
    int iend = istart + AGG_CHUNK;
    if (iend > NN) iend = NN;

    int curg = -1;
    float pl[8];
#pragma unroll
    for (int j = 0; j < 8; j++) pl[j] = 0.f;

    for (int i = istart; i < iend; i++) {
        float a0[8], a1[8];
#pragma unroll
        for (int j = 0; j < 8; j++) { a0[j] = 0.f; a1[j] = 0.f; }
        if (half == 0) {            // self term once
            uint4 u = xs4[(long long)i * 16 + li];
            acc8(u, a0);
        }
        int e0 = g_rowptr[i], e1 = g_rowptr[i + 1];
        int e = e0 + half;          // each half strides by 2
        for (; e + 4 <= e1; e += 4) {
            int sA = g_csrc[e], sB = g_csrc[e + 2];
            uint4 vA = xs4[(long long)sA * 16 + li];
            uint4 vB = xs4[(long long)sB * 16 + li];
            acc8(vA, a0);
            acc8(vB, a1);
        }
        for (; e < e1; e += 2) {
            int s = g_csrc[e];
            uint4 v = xs4[(long long)s * 16 + li];
            acc8(v, a0);
        }
        float d = g_dis[i];
        float y[8];
#pragma unroll
        for (int j = 0; j < 8; j++) {
            float a = a0[j] + a1[j];
            a += __shfl_xor_sync(0xffffffffu, a, 16);
            y[j] = fmaxf(fmaf(d, a, bl[j]), 0.f);
        }
        if (half == 0) {
            if (!LAST) {
                uint4 o;
                o.x = pack2(y[0], y[1]); o.y = pack2(y[2], y[3]);
                o.z = pack2(y[4], y[5]); o.w = pack2(y[6], y[7]);
                ((uint4*)g_h16)[(long long)i * 16 + li] = o;
            } else {
                int g = (int)idx_at(batch, i);
                if (g != curg) {
                    if (curg >= 0) {
                        float* p = &g_pool[curg * HH + li * 8];
#pragma unroll
                        for (int j = 0; j < 8; j++) atomicAdd(p + j, pl[j]);
                    }
                    curg = g;
#pragma unroll
                    for (int j = 0; j < 8; j++) pl[j] = 0.f;
                }
#pragma unroll
                for (int j = 0; j < 8; j++) pl[j] += y[j];
            }
#pragma unroll
            for (int j = 0; j < 8; j++) { st[j] += y[j]; qt[j] += y[j] * y[j]; }
        }
    }
    if (LAST && half == 0 && curg >= 0) {
        float* p = &g_pool[curg * HH + li * 8];
#pragma unroll
        for (int j = 0; j < 8; j++) atomicAdd(p + j, pl[j]);
    }
    __shared__ float red[2 * HH];
    red[tid] = 0.f;
    __syncthreads();
    if (half == 0) {
#pragma unroll
        for (int j = 0; j < 8; j++) {
            atomicAdd(&red[li * 8 + j], st[j]);
            atomicAdd(&red[HH + li * 8 + j], qt[j]);
        }
    }
    __syncthreads();
    atomicAdd(&g_stats[tid], red[tid]);
    __threadfence();
    __syncthreads();
    __shared__ int isLast;
    if (tid == 0)
        isLast = (atomicAdd(&g_arr, 1u) == (unsigned)(AGG_BLOCKS - 1)) ? 1 : 0;
    __syncthreads();
    if (isLast) {
        if (tid < HH) {
            float m = g_stats[tid] * (1.0f / NN);
            float v = g_stats[HH + tid] * (1.0f / NN) - m * m;
            v = fmaxf(v, 0.f);
            float s = gamma[tid] * rsqrtf(v + 1e-5f);
            g_bns[tid] = s;
            g_bnt[tid] = beta[tid] - m * s;
            g_stats[tid] = 0.f;
            g_stats[HH + tid] = 0.f;
        }
        if (tid == 0) g_arr = 0u;
        if (LAST) {
            __syncthreads();
            int g = tid;
            int c = lb_batch(batch, g + 1) - lb_batch(batch, g);
            float cnt = fmaxf((float)c, 1.0f);
            float r0 = bc[0], r1 = bc[1];
#pragma unroll 4
            for (int j = 0; j < HH; j++) {
                float p = g_pool[g * HH + j] / cnt;
                p = fmaf(p, g_bns[j], g_bnt[j]);
                r0 = fmaf(p, Wc[j * KK + 0], r0);
                r1 = fmaf(p, Wc[j * KK + 1], r1);
            }
#pragma unroll
            for (int j = 0; j < CC; j++) {
                float cl = clinical[g * CC + j];
                r0 = fmaf(cl, Wc[(HH + j) * KK + 0], r0);
                r1 = fmaf(cl, Wc[(HH + j) * KK + 1], r1);
            }
            out[g * KK + 0] = r0;
            out[g * KK + 1] = r1;
        }
    }
}

// ---------------- launch ----------------
extern "C" void kernel_launch(void* const* d_in, const int* in_sizes, int n_in,
                              void* d_out, int out_size) {
    const float* x        = (const float*)d_in[0];
    const void*  ei       = d_in[1];
    const void*  batch    = d_in[2];
    const float* clinical = (const float*)d_in[3];
    const float* W1 = (const float*)d_in[4];  const float* b1 = (const float*)d_in[5];
    const float* W2 = (const float*)d_in[6];  const float* b2 = (const float*)d_in[7];
    const float* W3 = (const float*)d_in[8];  const float* b3 = (const float*)d_in[9];
    const float* g1 = (const float*)d_in[10]; const float* be1 = (const float*)d_in[11];
    const float* g2 = (const float*)d_in[12]; const float* be2 = (const float*)d_in[13];
    const float* g3 = (const float*)d_in[14]; const float* be3 = (const float*)d_in[15];
    const float* Wc = (const float*)d_in[16]; const float* bc = (const float*)d_in[17];
    float* out = (float*)d_out;

    const size_t smem0 = SMEM0_U32 * sizeof(uint32_t);   // 30 KB
    const size_t smem1 = SMEM1_U32 * sizeof(uint32_t);   // 60 KB

    cudaFuncSetAttribute(k_gemm_tc<0>,
                         cudaFuncAttributeMaxDynamicSharedMemorySize, (int)smem0);
    cudaFuncSetAttribute(k_gemm_tc<1>,
                         cudaFuncAttributeMaxDynamicSharedMemorySize, (int)smem1);

    k_init_hist<<<PRE_BLOCKS, 256>>>((const int*)ei, ei, W1);            // 1
    k_scan_place<<<PRE_BLOCKS, 256>>>(ei);                               // 2
    k_gemm_tc<0><<<GEMM_BLOCKS, 256, smem0>>>(x);                        // 3
    k_agg<false><<<AGG_BLOCKS, 256>>>(b1, batch, g1, be1,
                                      nullptr, nullptr, nullptr, nullptr); // 4 (profiled)

    k_prepw_aff_r<<<65, 256>>>(W2);                                      // 5
    k_gemm_tc<1><<<GEMM_BLOCKS, 256, smem1>>>(nullptr);                  // 6
    k_agg<false><<<AGG_BLOCKS, 256>>>(b2, batch, g2, be2,
                                      nullptr, nullptr, nullptr, nullptr); // 7

    k_prepw_aff_r<<<65, 256>>>(W3);                                      // 8
    k_gemm_tc<1><<<GEMM_BLOCKS, 256, smem1>>>(nullptr);                  // 9
    k_agg<true><<<AGG_BLOCKS, 256>>>(b3, batch, g3, be3,
                                     clinical, Wc, bc, out);             // 10
}

// round 15
// speedup vs baseline: 1.3333x; 1.1932x over previous
#include <cuda_runtime.h>
#include <cuda_fp16.h>
#include <cstdint>

#define NN 100000
#define EE 1600000
#define HH 128
#define GG 256
#define CC 16
#define KK 2

#define PRE_BLOCKS ((NN + 255) / 256)    // 391 (single wave, grid-barrier safe)
#define GEMM_BLOCKS ((NN + 127) / 128)   // 782
#define AGG_BLOCKS 1024
#define AGG_WARPS (AGG_BLOCKS * 8)
#define AGG_CHUNK ((NN + AGG_WARPS - 1) / AGG_WARPS)   // 13

// ---------------- device scratch (static, allowed) ----------------
__device__ __half g_xs16[(size_t)NN * HH];
__device__ __half g_h16 [(size_t)NN * HH];
__device__ float g_dis[NN];
__device__ int   g_deg[NN];
__device__ int   g_rowptr[NN + 1];
__device__ int   g_cursor[NN];
__device__ int   g_csrc[EE];
__device__ float g_stats[2 * HH];
__device__ float g_bns[HH];
__device__ float g_bnt[HH];
__device__ float g_pool[GG * HH];
__device__ int   g_i64;
__device__ int   g_blk[PRE_BLOCKS + 8];
__device__ int   g_blkoff[PRE_BLOCKS + 8];
__device__ __half g_wh[HH * HH];           // W'^T hi fp16 [n][k]
__device__ __half g_wl[HH * HH];           // W'^T lo fp16 residual [n][k]
__device__ float g_wr[HH];
__device__ unsigned g_arr;                 // agg last-block counter
__device__ volatile unsigned g_gen;        // generation grid barrier
__device__ unsigned g_gcnt;

__device__ __forceinline__ void gsync(unsigned nblk) {
    __syncthreads();
    if (threadIdx.x == 0) {
        __threadfence();
        unsigned gen = g_gen;
        if (atomicAdd(&g_gcnt, 1u) == nblk - 1u) {
            g_gcnt = 0u;
            __threadfence();
            g_gen = gen + 1u;
        } else {
            while (g_gen == gen) __nanosleep(32);
        }
        __threadfence();
    }
    __syncthreads();
}

__device__ __forceinline__ long long idx_at(const void* p, long long i) {
    if (g_i64) return ((const long long*)p)[i];
    return (long long)((const int*)p)[i];
}

__device__ __forceinline__ void mma_f16(float* c, const uint32_t* a,
                                        uint32_t b0, uint32_t b1) {
    asm volatile(
        "mma.sync.aligned.m16n8k16.row.col.f32.f16.f16.f32 "
        "{%0,%1,%2,%3}, {%4,%5,%6,%7}, {%8,%9}, {%0,%1,%2,%3};\n"
        : "+f"(c[0]), "+f"(c[1]), "+f"(c[2]), "+f"(c[3])
        : "r"(a[0]), "r"(a[1]), "r"(a[2]), "r"(a[3]), "r"(b0), "r"(b1));
}

__device__ __forceinline__ void ldsm4(uint32_t& r0, uint32_t& r1,
                                      uint32_t& r2, uint32_t& r3, uint32_t addr) {
    asm volatile("ldmatrix.sync.aligned.m8n8.x4.shared.b16 {%0,%1,%2,%3}, [%4];"
                 : "=r"(r0), "=r"(r1), "=r"(r2), "=r"(r3) : "r"(addr));
}

__device__ __forceinline__ uint32_t pack2(float a, float b) {
    __half2 h = __floats2half2_rn(a, b);
    return *(uint32_t*)&h;
}

__device__ __forceinline__ void cpa16(uint32_t dst, const void* src, bool pred) {
    asm volatile("cp.async.cg.shared.global [%0], [%1], 16, %2;\n"
                 :: "r"(dst), "l"(src), "r"(pred ? 16 : 0));
}
__device__ __forceinline__ void cpa_commit() {
    asm volatile("cp.async.commit_group;\n");
}
template<int N>
__device__ __forceinline__ void cpa_wait() {
    asm volatile("cp.async.wait_group %0;\n" :: "n"(N));
}

// ====== launch 1: init (zero + detect + W1 prep) -> barrier -> histogram ======
__global__ void __launch_bounds__(256) k_init_hist(const int* ei32, const void* ei,
                                                   const float* __restrict__ W1) {
    int tid = threadIdx.x, b = blockIdx.x;
    int i = b * 256 + tid;
    if (b == 0 && tid < 32) {
        int lane = tid;
        int v = ei32[2 * lane + 1] | ei32[2 * (lane + 32) + 1] |
                ei32[2 * (lane + 64) + 1] | ei32[2 * (lane + 96) + 1];
        unsigned m = __ballot_sync(0xffffffffu, v != 0);
        if (lane == 0) g_i64 = (m == 0) ? 1 : 0;
    }
    if (i < NN) g_deg[i] = 0;
    if (i < GG * HH) g_pool[i] = 0.f;
    if (i < 2 * HH) g_stats[i] = 0.f;
    if (i == 0) g_arr = 0u;
    if (b == 1 && tid < HH) g_wr[tid] = 0.f;
    if (b < 64) {
        int idx = b * 256 + tid;
        int k = idx >> 7, n = idx & 127;
        float v = W1[idx];
        __half h = __float2half_rn(v);
        g_wh[n * HH + k] = h;
        g_wl[n * HH + k] = __float2half_rn(v - __half2float(h));
    }
    gsync(PRE_BLOCKS);
    for (long long e = (long long)b * 256 + tid; e < EE;
         e += (long long)PRE_BLOCKS * 256) {
        int d = (int)idx_at(ei, (long long)EE + e);
        atomicAdd(&g_deg[d], 1);
    }
}

// ====== launch 2: scan (rowptr/cursor/dis) -> barrier -> CSR place ======
__global__ void __launch_bounds__(256) k_scan_place(const void* ei) {
    int tid = threadIdx.x, b = blockIdx.x;
    int i = b * 256 + tid;
    int v = (i < NN) ? g_deg[i] : 0;
    float dis = rsqrtf((float)v + 1.0f);
    int x = v;
#pragma unroll
    for (int o = 1; o < 32; o <<= 1) {
        int y = __shfl_up_sync(0xffffffffu, x, o);
        if ((tid & 31) >= o) x += y;
    }
    __shared__ int ws[8];
    if ((tid & 31) == 31) ws[tid >> 5] = x;
    __syncthreads();
    if (tid < 8) {
        int s = ws[tid];
#pragma unroll
        for (int o = 1; o < 8; o <<= 1) {
            int y = __shfl_up_sync(0xffu, s, o);
            if (tid >= o) s += y;
        }
        ws[tid] = s;
    }
    __syncthreads();
    int warpoff = (tid >= 32) ? ws[(tid >> 5) - 1] : 0;
    if (tid == 0) g_blk[b] = ws[7];
    gsync(PRE_BLOCKS);
    if (b == 0) {
        __shared__ int s[256];
        int i0 = 2 * tid, i1 = 2 * tid + 1;
        int v0 = (i0 < PRE_BLOCKS) ? g_blk[i0] : 0;
        int v1 = (i1 < PRE_BLOCKS) ? g_blk[i1] : 0;
        int p = v0 + v1;
        s[tid] = p;
        __syncthreads();
        for (int d = 1; d < 256; d <<= 1) {
            int xx = (tid >= d) ? s[tid - d] : 0;
            __syncthreads();
            s[tid] += xx;
            __syncthreads();
        }
        int excl = s[tid] - p;
        if (i0 < PRE_BLOCKS) g_blkoff[i0] = excl;
        if (i1 < PRE_BLOCKS) g_blkoff[i1] = excl + v0;
        if (tid == 255) g_rowptr[NN] = s[255];
    }
    gsync(PRE_BLOCKS);
    int excl = x - v + warpoff + g_blkoff[b];
    if (i < NN) {
        g_rowptr[i] = excl;
        g_cursor[i] = excl;
        g_dis[i] = dis;
    }
    gsync(PRE_BLOCKS);
    for (long long e = (long long)b * 256 + tid; e < EE;
         e += (long long)PRE_BLOCKS * 256) {
        int d = (int)idx_at(ei, (long long)EE + e);
        int pos = atomicAdd(&g_cursor[d], 1);
        g_csrc[pos] = (int)idx_at(ei, e);
    }
}

__global__ void k_prepw_aff_r(const float* __restrict__ W) {
    if (blockIdx.x < 64) {
        int idx = blockIdx.x * 256 + threadIdx.x;
        int k = idx >> 7, n = idx & 127;
        float v = W[idx] * g_bns[k];
        __half h = __float2half_rn(v);
        g_wh[n * HH + k] = h;
        g_wl[n * HH + k] = __float2half_rn(v - __half2float(h));
    } else if (threadIdx.x < HH) {
        int n = threadIdx.x;
        float r = 0.f;
#pragma unroll 4
        for (int k = 0; k < HH; k++) r = fmaf(g_bnt[k], W[k * HH + n], r);
        g_wr[n] = r;
    }
}

// ---------------- fp16 tensor-core GEMM (unchanged) ----------------
#define ST 20
#define TS (128 * ST)
#define SW_H0 TS
#define SW_L0 (2 * TS)
#define SMEM0_U32 (3 * TS)          // 30 KB
#define BUFS (3 * TS)
#define SMEM1_U32 (2 * BUFS)        // 60 KB

template<int MODE>
__global__ void __launch_bounds__(256, 2) k_gemm_tc(const float* __restrict__ Ain) {
    extern __shared__ uint32_t sm[];
    int tid = threadIdx.x;
    int wid = tid >> 5, lane = tid & 31;
    int wm = wid >> 1, wn = wid & 1;
    int rbase = blockIdx.x * 128;
    uint32_t sbase = (uint32_t)__cvta_generic_to_shared((void*)sm);

    int asub = lane >> 3, ai = lane & 7;
    int a_row = (asub & 1) * 8 + ai;
    int a_k4  = (asub >> 1) * 4;
    int aoff0 = (wm * 32 + a_row) * ST + a_k4;
    int aoff1 = (wm * 32 + 16 + a_row) * ST + a_k4;
    int bsel = lane >> 4;
    int brow = lane & 7;
    int b_k4 = ((lane >> 3) & 1) * 4;
    int boff = (wn * 64 + brow) * ST + b_k4;

    float acc[2][8][4];
#pragma unroll
    for (int mt = 0; mt < 2; mt++)
#pragma unroll
        for (int j = 0; j < 8; j++)
#pragma unroll
            for (int q = 0; q < 4; q++) acc[mt][j][q] = 0.f;

    if (MODE == 0) {
        int btile = boff + (bsel ? SW_L0 : SW_H0);
        for (int ch = 0; ch < 4; ch++) {
            int kbase = ch * 32;
#pragma unroll
            for (int i = 0; i < 2; i++) {
                int idx = i * 256 + tid;
                int m = idx >> 2, q = idx & 3;
                int gr = rbase + m;
                float4 v0 = make_float4(0.f, 0.f, 0.f, 0.f);
                float4 v1 = make_float4(0.f, 0.f, 0.f, 0.f);
                if (gr < NN) {
                    v0 = *(const float4*)&Ain[(size_t)gr * HH + kbase + 8 * q];
                    v1 = *(const float4*)&Ain[(size_t)gr * HH + kbase + 8 * q + 4];
                }
                *(uint4*)&sm[m * ST + 4 * q] = make_uint4(
                    pack2(v0.x, v0.y), pack2(v0.z, v0.w),
                    pack2(v1.x, v1.y), pack2(v1.z, v1.w));
            }
#pragma unroll
            for (int i = 0; i < 2; i++) {
                int idx = i * 256 + tid;
                int n = idx >> 2, q = idx & 3;
                *(uint4*)&sm[SW_H0 + n * ST + 4 * q] =
                    *(const uint4*)&g_wh[n * HH + kbase + 8 * q];
                *(uint4*)&sm[SW_L0 + n * ST + 4 * q] =
                    *(const uint4*)&g_wl[n * HH + kbase + 8 * q];
            }
            __syncthreads();
#pragma unroll
            for (int ks = 0; ks < 2; ks++) {
                int koff = ks * 8;
                uint32_t ah[2][4];
                ldsm4(ah[0][0], ah[0][1], ah[0][2], ah[0][3],
                      sbase + 4 * (aoff0 + koff));
                ldsm4(ah[1][0], ah[1][1], ah[1][2], ah[1][3],
                      sbase + 4 * (aoff1 + koff));
#pragma unroll
                for (int j = 0; j < 8; j++) {
                    uint32_t bh0, bh1, bl0, bl1;
                    ldsm4(bh0, bh1, bl0, bl1,
                          sbase + 4 * (btile + j * 8 * ST + koff));
#pragma unroll
                    for (int mt = 0; mt < 2; mt++) {
                        mma_f16(acc[mt][j], ah[mt], bh0, bh1);
                        mma_f16(acc[mt][j], ah[mt], bl0, bl1);
                    }
                }
            }
            __syncthreads();
        }
    } else {
        int btile = boff + TS + bsel * TS;
        int m_ = tid >> 2, q_ = tid & 3;
        int m2 = (256 + tid) >> 2, q2 = (256 + tid) & 3;
#define ISSUE_CHUNK(CH, BUF) { \
        int kb = (CH) * 32; int bo = (BUF) * BUFS; \
        { int gr = rbase + m_; bool p = gr < NN; \
          const __half* s = p ? &g_h16[(size_t)gr * HH + kb + 8 * q_] : &g_h16[0]; \
          cpa16(sbase + 4 * (bo + m_ * ST + 4 * q_), s, p); } \
        { int gr = rbase + m2; bool p = gr < NN; \
          const __half* s = p ? &g_h16[(size_t)gr * HH + kb + 8 * q2] : &g_h16[0]; \
          cpa16(sbase + 4 * (bo + m2 * ST + 4 * q2), s, p); } \
        cpa16(sbase + 4 * (bo + TS + m_ * ST + 4 * q_),      &g_wh[m_ * HH + kb + 8 * q_], true); \
        cpa16(sbase + 4 * (bo + TS + m2 * ST + 4 * q2),      &g_wh[m2 * HH + kb + 8 * q2], true); \
        cpa16(sbase + 4 * (bo + 2 * TS + m_ * ST + 4 * q_),  &g_wl[m_ * HH + kb + 8 * q_], true); \
        cpa16(sbase + 4 * (bo + 2 * TS + m2 * ST + 4 * q2),  &g_wl[m2 * HH + kb + 8 * q2], true); \
        cpa_commit(); }

        ISSUE_CHUNK(0, 0);
#pragma unroll
        for (int ch = 0; ch < 4; ch++) {
            int buf = ch & 1;
            if (ch < 3) { ISSUE_CHUNK(ch + 1, buf ^ 1); cpa_wait<1>(); }
            else cpa_wait<0>();
            __syncthreads();
            int bo = buf * BUFS;
#pragma unroll
            for (int ks = 0; ks < 2; ks++) {
                int koff = ks * 8;
                uint32_t ah[2][4];
                ldsm4(ah[0][0], ah[0][1], ah[0][2], ah[0][3],
                      sbase + 4 * (bo + aoff0 + koff));
                ldsm4(ah[1][0], ah[1][1], ah[1][2], ah[1][3],
                      sbase + 4 * (bo + aoff1 + koff));
#pragma unroll
                for (int j = 0; j < 8; j++) {
                    uint32_t bh0, bh1, bl0, bl1;
                    ldsm4(bh0, bh1, bl0, bl1,
                          sbase + 4 * (bo + btile + j * 8 * ST + koff));
#pragma unroll
                    for (int mt = 0; mt < 2; mt++) {
                        mma_f16(acc[mt][j], ah[mt], bh0, bh1);
                        mma_f16(acc[mt][j], ah[mt], bl0, bl1);
                    }
                }
            }
            __syncthreads();
        }
#undef ISSUE_CHUNK
    }

    int ly = lane >> 2, lx = lane & 3;
#pragma unroll
    for (int mt = 0; mt < 2; mt++) {
        int r0 = rbase + wm * 32 + mt * 16 + ly;
        int r1 = r0 + 8;
        float d0 = (r0 < NN) ? g_dis[r0] : 0.f;
        float d1 = (r1 < NN) ? g_dis[r1] : 0.f;
#pragma unroll
        for (int j = 0; j < 8; j++) {
            int cb = wn * 64 + 8 * j + 2 * lx;
            float ra = g_wr[cb], rb = g_wr[cb + 1];
            if (r0 < NN) {
                __half2 o = __floats2half2_rn(d0 * (acc[mt][j][0] + ra),
                                              d0 * (acc[mt][j][1] + rb));
                *(__half2*)&g_xs16[(size_t)r0 * HH + cb] = o;
            }
            if (r1 < NN) {
                __half2 o = __floats2half2_rn(d1 * (acc[mt][j][2] + ra),
                                              d1 * (acc[mt][j][3] + rb));
                *(__half2*)&g_xs16[(size_t)r1 * HH + cb] = o;
            }
        }
    }
}

// ------- aggregation: half2-native accumulation (2 HADD2 per edge per lane) -------
__device__ __forceinline__ int lb_batch(const void* batch, int val) {
    int lo = 0, hi = NN;
    while (lo < hi) {
        int mid = (lo + hi) >> 1;
        if ((int)idx_at(batch, mid) < val) lo = mid + 1;
        else hi = mid;
    }
    return lo;
}

template<bool LAST>
__global__ void __launch_bounds__(256) k_agg(const float* __restrict__ bias,
                                             const void* __restrict__ batch,
                                             const float* __restrict__ gamma,
                                             const float* __restrict__ beta,
                                             const float* __restrict__ clinical,
                                             const float* __restrict__ Wc,
                                             const float* __restrict__ bc,
                                             float* __restrict__ out) {
    int tid = threadIdx.x;
    int wid = tid >> 5, lane = tid & 31;
    float4 b4 = ((const float4*)bias)[lane];
    float s0 = 0.f, s1 = 0.f, s2 = 0.f, s3 = 0.f;
    float q0 = 0.f, q1 = 0.f, q2 = 0.f, q3 = 0.f;
    const uint2* xsv = (const uint2*)g_xs16;

    int wgl = blockIdx.x * 8 + wid;
    int istart = wgl * AGG_CHUNK;
    int iend = istart + AGG_CHUNK;
    if (iend > NN) iend = NN;

    int curg = -1;
    float px = 0.f, py = 0.f, pz = 0.f, pw = 0.f;
    const __half2 hz = __floats2half2_rn(0.f, 0.f);

    for (int i = istart; i < iend; i++) {
        uint2 u = xsv[(long long)i * 32 + lane];      // self term -> set 0
        __half2 A0x = *(__half2*)&u.x, A0y = *(__half2*)&u.y;
        __half2 A1x = hz, A1y = hz;
        int e0 = g_rowptr[i], e1 = g_rowptr[i + 1];
        int e = e0;
        for (; e + 4 <= e1; e += 4) {
            int sA = g_csrc[e], sB = g_csrc[e + 1];
            int sC = g_csrc[e + 2], sD = g_csrc[e + 3];
            uint2 vA = xsv[(long long)sA * 32 + lane];
            uint2 vB = xsv[(long long)sB * 32 + lane];
            uint2 vC = xsv[(long long)sC * 32 + lane];
            uint2 vD = xsv[(long long)sD * 32 + lane];
            A0x = __hadd2(A0x, *(__half2*)&vA.x); A0y = __hadd2(A0y, *(__half2*)&vA.y);
            A1x = __hadd2(A1x, *(__half2*)&vB.x); A1y = __hadd2(A1y, *(__half2*)&vB.y);
            A0x = __hadd2(A0x, *(__half2*)&vC.x); A0y = __hadd2(A0y, *(__half2*)&vC.y);
            A1x = __hadd2(A1x, *(__half2*)&vD.x); A1y = __hadd2(A1y, *(__half2*)&vD.y);
        }
        for (; e < e1; e++) {
            int s = g_csrc[e];
            uint2 v = xsv[(long long)s * 32 + lane];
            A0x = __hadd2(A0x, *(__half2*)&v.x);
            A0y = __hadd2(A0y, *(__half2*)&v.y);
        }
        float2 f0 = __half22float2(A0x), f1 = __half22float2(A1x);
        float2 g0 = __half22float2(A0y), g1 = __half22float2(A1y);
        float acx = f0.x + f1.x, acy = f0.y + f1.y;
        float acz = g0.x + g1.x, acw = g0.y + g1.y;
        float d = g_dis[i];
        float yx = fmaxf(fmaf(d, acx, b4.x), 0.f);
        float yy = fmaxf(fmaf(d, acy, b4.y), 0.f);
        float yz = fmaxf(fmaf(d, acz, b4.z), 0.f);
        float yw = fmaxf(fmaf(d, acw, b4.w), 0.f);
        if (!LAST) {
            uint2 o;
            *(__half2*)&o.x = __floats2half2_rn(yx, yy);
            *(__half2*)&o.y = __floats2half2_rn(yz, yw);
            ((uint2*)g_h16)[(long long)i * 32 + lane] = o;
        } else {
            int g = (int)idx_at(batch, i);
            if (g != curg) {
                if (curg >= 0) {
                    float* p = &g_pool[curg * HH + lane * 4];
                    atomicAdd(p + 0, px); atomicAdd(p + 1, py);
                    atomicAdd(p + 2, pz); atomicAdd(p + 3, pw);
                }
                curg = g; px = py = pz = pw = 0.f;
            }
            px += yx; py += yy; pz += yz; pw += yw;
        }
        s0 += yx; s1 += yy; s2 += yz; s3 += yw;
        q0 += yx * yx; q1 += yy * yy; q2 += yz * yz; q3 += yw * yw;
    }
    if (LAST && curg >= 0) {
        float* p = &g_pool[curg * HH + lane * 4];
        atomicAdd(p + 0, px); atomicAdd(p + 1, py);
        atomicAdd(p + 2, pz); atomicAdd(p + 3, pw);
    }
    __shared__ float red[2 * HH];
    red[tid] = 0.f;
    __syncthreads();
    atomicAdd(&red[lane * 4 + 0], s0);
    atomicAdd(&red[lane * 4 + 1], s1);
    atomicAdd(&red[lane * 4 + 2], s2);
    atomicAdd(&red[lane * 4 + 3], s3);
    atomicAdd(&red[HH + lane * 4 + 0], q0);
    atomicAdd(&red[HH + lane * 4 + 1], q1);
    atomicAdd(&red[HH + lane * 4 + 2], q2);
    atomicAdd(&red[HH + lane * 4 + 3], q3);
    __syncthreads();
    atomicAdd(&g_stats[tid], red[tid]);
    __threadfence();
    __syncthreads();
    __shared__ int isLast;
    if (tid == 0)
        isLast = (atomicAdd(&g_arr, 1u) == (unsigned)(AGG_BLOCKS - 1)) ? 1 : 0;
    __syncthreads();
    if (isLast) {
        if (tid < HH) {
            float m = g_stats[tid] * (1.0f / NN);
            float v = g_stats[HH + tid] * (1.0f / NN) - m * m;
            v = fmaxf(v, 0.f);
            float s = gamma[tid] * rsqrtf(v + 1e-5f);
            g_bns[tid] = s;
            g_bnt[tid] = beta[tid] - m * s;
            g_stats[tid] = 0.f;
            g_stats[HH + tid] = 0.f;
        }
        if (tid == 0) g_arr = 0u;
        if (LAST) {
            __syncthreads();
            int g = tid;
            int c = lb_batch(batch, g + 1) - lb_batch(batch, g);
            float cnt = fmaxf((float)c, 1.0f);
            float r0 = bc[0], r1 = bc[1];
#pragma unroll 4
            for (int j = 0; j < HH; j++) {
                float p = g_pool[g * HH + j] / cnt;
                p = fmaf(p, g_bns[j], g_bnt[j]);
                r0 = fmaf(p, Wc[j * KK + 0], r0);
                r1 = fmaf(p, Wc[j * KK + 1], r1);
            }
#pragma unroll
            for (int j = 0; j < CC; j++) {
                float cl = clinical[g * CC + j];
                r0 = fmaf(cl, Wc[(HH + j) * KK + 0], r0);
                r1 = fmaf(cl, Wc[(HH + j) * KK + 1], r1);
            }
            out[g * KK + 0] = r0;
            out[g * KK + 1] = r1;
        }
    }
}

// ---------------- launch ----------------
extern "C" void kernel_launch(void* const* d_in, const int* in_sizes, int n_in,
                              void* d_out, int out_size) {
    const float* x        = (const float*)d_in[0];
    const void*  ei       = d_in[1];
    const void*  batch    = d_in[2];
    const float* clinical = (const float*)d_in[3];
    const float* W1 = (const float*)d_in[4];  const float* b1 = (const float*)d_in[5];
    const float* W2 = (const float*)d_in[6];  const float* b2 = (const float*)d_in[7];
    const float* W3 = (const float*)d_in[8];  const float* b3 = (const float*)d_in[9];
    const float* g1 = (const float*)d_in[10]; const float* be1 = (const float*)d_in[11];
    const float* g2 = (const float*)d_in[12]; const float* be2 = (const float*)d_in[13];
    const float* g3 = (const float*)d_in[14]; const float* be3 = (const float*)d_in[15];
    const float* Wc = (const float*)d_in[16]; const float* bc = (const float*)d_in[17];
    float* out = (float*)d_out;

    const size_t smem0 = SMEM0_U32 * sizeof(uint32_t);   // 30 KB
    const size_t smem1 = SMEM1_U32 * sizeof(uint32_t);   // 60 KB

    cudaFuncSetAttribute(k_gemm_tc<0>,
                         cudaFuncAttributeMaxDynamicSharedMemorySize, (int)smem0);
    cudaFuncSetAttribute(k_gemm_tc<1>,
                         cudaFuncAttributeMaxDynamicSharedMemorySize, (int)smem1);

    k_init_hist<<<PRE_BLOCKS, 256>>>((const int*)ei, ei, W1);            // 1
    k_scan_place<<<PRE_BLOCKS, 256>>>(ei);                               // 2
    k_gemm_tc<0><<<GEMM_BLOCKS, 256, smem0>>>(x);                        // 3
    k_agg<false><<<AGG_BLOCKS, 256>>>(b1, batch, g1, be1,
                                      nullptr, nullptr, nullptr, nullptr); // 4 (profiled)

    k_prepw_aff_r<<<65, 256>>>(W2);                                      // 5
    k_gemm_tc<1><<<GEMM_BLOCKS, 256, smem1>>>(nullptr);                  // 6
    k_agg<false><<<AGG_BLOCKS, 256>>>(b2, batch, g2, be2,
                                      nullptr, nullptr, nullptr, nullptr); // 7

    k_prepw_aff_r<<<65, 256>>>(W3);                                      // 8
    k_gemm_tc<1><<<GEMM_BLOCKS, 256, smem1>>>(nullptr);                  // 9
    k_agg<true><<<AGG_BLOCKS, 256>>>(b3, batch, g3, be3,
                                     clinical, Wc, bc, out);             // 10
}

// round 16
// speedup vs baseline: 1.5163x; 1.1373x over previous
#include <cuda_runtime.h>
#include <cuda_fp16.h>
#include <cstdint>

#define NN 100000
#define EE 1600000
#define HH 128
#define GG 256
#define CC 16
#define KK 2

#define PRE_BLOCKS ((NN + 255) / 256)    // 391 (single wave, grid-barrier safe)
#define GEMM_BLOCKS ((NN + 127) / 128)   // 782
#define AGG_BLOCKS 888                   // 6 blocks/SM x 148 SMs = one full wave
#define AGG_WARPS (AGG_BLOCKS * 8)
#define AGG_CHUNK ((NN + AGG_WARPS - 1) / AGG_WARPS)   // 15

// ---------------- device scratch (static, allowed) ----------------
__device__ __half g_xs16[(size_t)NN * HH];
__device__ __half g_h16 [(size_t)NN * HH];
__device__ float g_dis[NN];
__device__ int   g_deg[NN];
__device__ int   g_rowptr[NN + 1];
__device__ int   g_cursor[NN];
__device__ int   g_csrc[EE];
__device__ float g_stats[2 * HH];
__device__ float g_bns[HH];
__device__ float g_bnt[HH];
__device__ float g_pool[GG * HH];
__device__ int   g_i64;
__device__ int   g_blk[PRE_BLOCKS + 8];
__device__ int   g_blkoff[PRE_BLOCKS + 8];
__device__ __half g_wh[HH * HH];           // W'^T hi fp16 [n][k]
__device__ __half g_wl[HH * HH];           // W'^T lo fp16 residual [n][k]
__device__ float g_wr[HH];
__device__ unsigned g_arr;                 // agg last-block counter
__device__ volatile unsigned g_gen;        // generation grid barrier
__device__ unsigned g_gcnt;

__device__ __forceinline__ void gsync(unsigned nblk) {
    __syncthreads();
    if (threadIdx.x == 0) {
        __threadfence();
        unsigned gen = g_gen;
        if (atomicAdd(&g_gcnt, 1u) == nblk - 1u) {
            g_gcnt = 0u;
            __threadfence();
            g_gen = gen + 1u;
        } else {
            while (g_gen == gen) __nanosleep(32);
        }
        __threadfence();
    }
    __syncthreads();
}

__device__ __forceinline__ long long idx_at(const void* p, long long i) {
    if (g_i64) return ((const long long*)p)[i];
    return (long long)((const int*)p)[i];
}

__device__ __forceinline__ void mma_f16(float* c, const uint32_t* a,
                                        uint32_t b0, uint32_t b1) {
    asm volatile(
        "mma.sync.aligned.m16n8k16.row.col.f32.f16.f16.f32 "
        "{%0,%1,%2,%3}, {%4,%5,%6,%7}, {%8,%9}, {%0,%1,%2,%3};\n"
        : "+f"(c[0]), "+f"(c[1]), "+f"(c[2]), "+f"(c[3])
        : "r"(a[0]), "r"(a[1]), "r"(a[2]), "r"(a[3]), "r"(b0), "r"(b1));
}

__device__ __forceinline__ void ldsm4(uint32_t& r0, uint32_t& r1,
                                      uint32_t& r2, uint32_t& r3, uint32_t addr) {
    asm volatile("ldmatrix.sync.aligned.m8n8.x4.shared.b16 {%0,%1,%2,%3}, [%4];"
                 : "=r"(r0), "=r"(r1), "=r"(r2), "=r"(r3) : "r"(addr));
}

__device__ __forceinline__ uint32_t pack2(float a, float b) {
    __half2 h = __floats2half2_rn(a, b);
    return *(uint32_t*)&h;
}

__device__ __forceinline__ void cpa16(uint32_t dst, const void* src, bool pred) {
    asm volatile("cp.async.cg.shared.global [%0], [%1], 16, %2;\n"
                 :: "r"(dst), "l"(src), "r"(pred ? 16 : 0));
}
__device__ __forceinline__ void cpa_commit() {
    asm volatile("cp.async.commit_group;\n");
}
template<int N>
__device__ __forceinline__ void cpa_wait() {
    asm volatile("cp.async.wait_group %0;\n" :: "n"(N));
}

// ====== launch 1: init (zero + detect + W1 prep) -> barrier -> histogram ======
__global__ void __launch_bounds__(256) k_init_hist(const int* ei32, const void* ei,
                                                   const float* __restrict__ W1) {
    int tid = threadIdx.x, b = blockIdx.x;
    int i = b * 256 + tid;
    if (b == 0 && tid < 32) {
        int lane = tid;
        int v = ei32[2 * lane + 1] | ei32[2 * (lane + 32) + 1] |
                ei32[2 * (lane + 64) + 1] | ei32[2 * (lane + 96) + 1];
        unsigned m = __ballot_sync(0xffffffffu, v != 0);
        if (lane == 0) g_i64 = (m == 0) ? 1 : 0;
    }
    if (i < NN) g_deg[i] = 0;
    if (i < GG * HH) g_pool[i] = 0.f;
    if (i < 2 * HH) g_stats[i] = 0.f;
    if (i == 0) g_arr = 0u;
    if (b == 1 && tid < HH) g_wr[tid] = 0.f;
    if (b < 64) {
        int idx = b * 256 + tid;
        int k = idx >> 7, n = idx & 127;
        float v = W1[idx];
        __half h = __float2half_rn(v);
        g_wh[n * HH + k] = h;
        g_wl[n * HH + k] = __float2half_rn(v - __half2float(h));
    }
    gsync(PRE_BLOCKS);
    for (long long e = (long long)b * 256 + tid; e < EE;
         e += (long long)PRE_BLOCKS * 256) {
        int d = (int)idx_at(ei, (long long)EE + e);
        atomicAdd(&g_deg[d], 1);
    }
}

// ====== launch 2: scan (rowptr/cursor/dis) -> barrier -> CSR place ======
__global__ void __launch_bounds__(256) k_scan_place(const void* ei) {
    int tid = threadIdx.x, b = blockIdx.x;
    int i = b * 256 + tid;
    int v = (i < NN) ? g_deg[i] : 0;
    float dis = rsqrtf((float)v + 1.0f);
    int x = v;
#pragma unroll
    for (int o = 1; o < 32; o <<= 1) {
        int y = __shfl_up_sync(0xffffffffu, x, o);
        if ((tid & 31) >= o) x += y;
    }
    __shared__ int ws[8];
    if ((tid & 31) == 31) ws[tid >> 5] = x;
    __syncthreads();
    if (tid < 8) {
        int s = ws[tid];
#pragma unroll
        for (int o = 1; o < 8; o <<= 1) {
            int y = __shfl_up_sync(0xffu, s, o);
            if (tid >= o) s += y;
        }
        ws[tid] = s;
    }
    __syncthreads();
    int warpoff = (tid >= 32) ? ws[(tid >> 5) - 1] : 0;
    if (tid == 0) g_blk[b] = ws[7];
    gsync(PRE_BLOCKS);
    if (b == 0) {
        __shared__ int s[256];
        int i0 = 2 * tid, i1 = 2 * tid + 1;
        int v0 = (i0 < PRE_BLOCKS) ? g_blk[i0] : 0;
        int v1 = (i1 < PRE_BLOCKS) ? g_blk[i1] : 0;
        int p = v0 + v1;
        s[tid] = p;
        __syncthreads();
        for (int d = 1; d < 256; d <<= 1) {
            int xx = (tid >= d) ? s[tid - d] : 0;
            __syncthreads();
            s[tid] += xx;
            __syncthreads();
        }
        int excl = s[tid] - p;
        if (i0 < PRE_BLOCKS) g_blkoff[i0] = excl;
        if (i1 < PRE_BLOCKS) g_blkoff[i1] = excl + v0;
        if (tid == 255) g_rowptr[NN] = s[255];
    }
    gsync(PRE_BLOCKS);
    int excl = x - v + warpoff + g_blkoff[b];
    if (i < NN) {
        g_rowptr[i] = excl;
        g_cursor[i] = excl;
        g_dis[i] = dis;
    }
    gsync(PRE_BLOCKS);
    for (long long e = (long long)b * 256 + tid; e < EE;
         e += (long long)PRE_BLOCKS * 256) {
        int d = (int)idx_at(ei, (long long)EE + e);
        int pos = atomicAdd(&g_cursor[d], 1);
        g_csrc[pos] = (int)idx_at(ei, e);
    }
}

__global__ void k_prepw_aff_r(const float* __restrict__ W) {
    if (blockIdx.x < 64) {
        int idx = blockIdx.x * 256 + threadIdx.x;
        int k = idx >> 7, n = idx & 127;
        float v = W[idx] * g_bns[k];
        __half h = __float2half_rn(v);
        g_wh[n * HH + k] = h;
        g_wl[n * HH + k] = __float2half_rn(v - __half2float(h));
    } else if (threadIdx.x < HH) {
        int n = threadIdx.x;
        float r = 0.f;
#pragma unroll 4
        for (int k = 0; k < HH; k++) r = fmaf(g_bnt[k], W[k * HH + n], r);
        g_wr[n] = r;
    }
}

// ---------------- fp16 tensor-core GEMM (unchanged) ----------------
#define ST 20
#define TS (128 * ST)
#define SW_H0 TS
#define SW_L0 (2 * TS)
#define SMEM0_U32 (3 * TS)          // 30 KB
#define BUFS (3 * TS)
#define SMEM1_U32 (2 * BUFS)        // 60 KB

template<int MODE>
__global__ void __launch_bounds__(256, 2) k_gemm_tc(const float* __restrict__ Ain) {
    extern __shared__ uint32_t sm[];
    int tid = threadIdx.x;
    int wid = tid >> 5, lane = tid & 31;
    int wm = wid >> 1, wn = wid & 1;
    int rbase = blockIdx.x * 128;
    uint32_t sbase = (uint32_t)__cvta_generic_to_shared((void*)sm);

    int asub = lane >> 3, ai = lane & 7;
    int a_row = (asub & 1) * 8 + ai;
    int a_k4  = (asub >> 1) * 4;
    int aoff0 = (wm * 32 + a_row) * ST + a_k4;
    int aoff1 = (wm * 32 + 16 + a_row) * ST + a_k4;
    int bsel = lane >> 4;
    int brow = lane & 7;
    int b_k4 = ((lane >> 3) & 1) * 4;
    int boff = (wn * 64 + brow) * ST + b_k4;

    float acc[2][8][4];
#pragma unroll
    for (int mt = 0; mt < 2; mt++)
#pragma unroll
        for (int j = 0; j < 8; j++)
#pragma unroll
            for (int q = 0; q < 4; q++) acc[mt][j][q] = 0.f;

    if (MODE == 0) {
        int btile = boff + (bsel ? SW_L0 : SW_H0);
        for (int ch = 0; ch < 4; ch++) {
            int kbase = ch * 32;
#pragma unroll
            for (int i = 0; i < 2; i++) {
                int idx = i * 256 + tid;
                int m = idx >> 2, q = idx & 3;
                int gr = rbase + m;
                float4 v0 = make_float4(0.f, 0.f, 0.f, 0.f);
                float4 v1 = make_float4(0.f, 0.f, 0.f, 0.f);
                if (gr < NN) {
                    v0 = *(const float4*)&Ain[(size_t)gr * HH + kbase + 8 * q];
                    v1 = *(const float4*)&Ain[(size_t)gr * HH + kbase + 8 * q + 4];
                }
                *(uint4*)&sm[m * ST + 4 * q] = make_uint4(
                    pack2(v0.x, v0.y), pack2(v0.z, v0.w),
                    pack2(v1.x, v1.y), pack2(v1.z, v1.w));
            }
#pragma unroll
            for (int i = 0; i < 2; i++) {
                int idx = i * 256 + tid;
                int n = idx >> 2, q = idx & 3;
                *(uint4*)&sm[SW_H0 + n * ST + 4 * q] =
                    *(const uint4*)&g_wh[n * HH + kbase + 8 * q];
                *(uint4*)&sm[SW_L0 + n * ST + 4 * q] =
                    *(const uint4*)&g_wl[n * HH + kbase + 8 * q];
            }
            __syncthreads();
#pragma unroll
            for (int ks = 0; ks < 2; ks++) {
                int koff = ks * 8;
                uint32_t ah[2][4];
                ldsm4(ah[0][0], ah[0][1], ah[0][2], ah[0][3],
                      sbase + 4 * (aoff0 + koff));
                ldsm4(ah[1][0], ah[1][1], ah[1][2], ah[1][3],
                      sbase + 4 * (aoff1 + koff));
#pragma unroll
                for (int j = 0; j < 8; j++) {
                    uint32_t bh0, bh1, bl0, bl1;
                    ldsm4(bh0, bh1, bl0, bl1,
                          sbase + 4 * (btile + j * 8 * ST + koff));
#pragma unroll
                    for (int mt = 0; mt < 2; mt++) {
                        mma_f16(acc[mt][j], ah[mt], bh0, bh1);
                        mma_f16(acc[mt][j], ah[mt], bl0, bl1);
                    }
                }
            }
            __syncthreads();
        }
    } else {
        int btile = boff + TS + bsel * TS;
        int m_ = tid >> 2, q_ = tid & 3;
        int m2 = (256 + tid) >> 2, q2 = (256 + tid) & 3;
#define ISSUE_CHUNK(CH, BUF) { \
        int kb = (CH) * 32; int bo = (BUF) * BUFS; \
        { int gr = rbase + m_; bool p = gr < NN; \
          const __half* s = p ? &g_h16[(size_t)gr * HH + kb + 8 * q_] : &g_h16[0]; \
          cpa16(sbase + 4 * (bo + m_ * ST + 4 * q_), s, p); } \
        { int gr = rbase + m2; bool p = gr < NN; \
          const __half* s = p ? &g_h16[(size_t)gr * HH + kb + 8 * q2] : &g_h16[0]; \
          cpa16(sbase + 4 * (bo + m2 * ST + 4 * q2), s, p); } \
        cpa16(sbase + 4 * (bo + TS + m_ * ST + 4 * q_),      &g_wh[m_ * HH + kb + 8 * q_], true); \
        cpa16(sbase + 4 * (bo + TS + m2 * ST + 4 * q2),      &g_wh[m2 * HH + kb + 8 * q2], true); \
        cpa16(sbase + 4 * (bo + 2 * TS + m_ * ST + 4 * q_),  &g_wl[m_ * HH + kb + 8 * q_], true); \
        cpa16(sbase + 4 * (bo + 2 * TS + m2 * ST + 4 * q2),  &g_wl[m2 * HH + kb + 8 * q2], true); \
        cpa_commit(); }

        ISSUE_CHUNK(0, 0);
#pragma unroll
        for (int ch = 0; ch < 4; ch++) {
            int buf = ch & 1;
            if (ch < 3) { ISSUE_CHUNK(ch + 1, buf ^ 1); cpa_wait<1>(); }
            else cpa_wait<0>();
            __syncthreads();
            int bo = buf * BUFS;
#pragma unroll
            for (int ks = 0; ks < 2; ks++) {
                int koff = ks * 8;
                uint32_t ah[2][4];
                ldsm4(ah[0][0], ah[0][1], ah[0][2], ah[0][3],
                      sbase + 4 * (bo + aoff0 + koff));
                ldsm4(ah[1][0], ah[1][1], ah[1][2], ah[1][3],
                      sbase + 4 * (bo + aoff1 + koff));
#pragma unroll
                for (int j = 0; j < 8; j++) {
                    uint32_t bh0, bh1, bl0, bl1;
                    ldsm4(bh0, bh1, bl0, bl1,
                          sbase + 4 * (bo + btile + j * 8 * ST + koff));
#pragma unroll
                    for (int mt = 0; mt < 2; mt++) {
                        mma_f16(acc[mt][j], ah[mt], bh0, bh1);
                        mma_f16(acc[mt][j], ah[mt], bl0, bl1);
                    }
                }
            }
            __syncthreads();
        }
#undef ISSUE_CHUNK
    }

    int ly = lane >> 2, lx = lane & 3;
#pragma unroll
    for (int mt = 0; mt < 2; mt++) {
        int r0 = rbase + wm * 32 + mt * 16 + ly;
        int r1 = r0 + 8;
        float d0 = (r0 < NN) ? g_dis[r0] : 0.f;
        float d1 = (r1 < NN) ? g_dis[r1] : 0.f;
#pragma unroll
        for (int j = 0; j < 8; j++) {
            int cb = wn * 64 + 8 * j + 2 * lx;
            float ra = g_wr[cb], rb = g_wr[cb + 1];
            if (r0 < NN) {
                __half2 o = __floats2half2_rn(d0 * (acc[mt][j][0] + ra),
                                              d0 * (acc[mt][j][1] + rb));
                *(__half2*)&g_xs16[(size_t)r0 * HH + cb] = o;
            }
            if (r1 < NN) {
                __half2 o = __floats2half2_rn(d1 * (acc[mt][j][2] + ra),
                                              d1 * (acc[mt][j][3] + rb));
                *(__half2*)&g_xs16[(size_t)r1 * HH + cb] = o;
            }
        }
    }
}

// ------- aggregation: half2-native accumulation, single-wave grid -------
__device__ __forceinline__ int lb_batch(const void* batch, int val) {
    int lo = 0, hi = NN;
    while (lo < hi) {
        int mid = (lo + hi) >> 1;
        if ((int)idx_at(batch, mid) < val) lo = mid + 1;
        else hi = mid;
    }
    return lo;
}

template<bool LAST>
__global__ void __launch_bounds__(256, 6) k_agg(const float* __restrict__ bias,
                                                const void* __restrict__ batch,
                                                const float* __restrict__ gamma,
                                                const float* __restrict__ beta,
                                                const float* __restrict__ clinical,
                                                const float* __restrict__ Wc,
                                                const float* __restrict__ bc,
                                                float* __restrict__ out) {
    int tid = threadIdx.x;
    int wid = tid >> 5, lane = tid & 31;
    float4 b4 = ((const float4*)bias)[lane];
    float s0 = 0.f, s1 = 0.f, s2 = 0.f, s3 = 0.f;
    float q0 = 0.f, q1 = 0.f, q2 = 0.f, q3 = 0.f;
    const uint2* xsv = (const uint2*)g_xs16;

    int wgl = blockIdx.x * 8 + wid;
    int istart = wgl * AGG_CHUNK;
    int iend = istart + AGG_CHUNK;
    if (iend > NN) iend = NN;

    int curg = -1;
    float px = 0.f, py = 0.f, pz = 0.f, pw = 0.f;
    const __half2 hz = __floats2half2_rn(0.f, 0.f);

    for (int i = istart; i < iend; i++) {
        uint2 u = xsv[(long long)i * 32 + lane];      // self term -> set 0
        __half2 A0x = *(__half2*)&u.x, A0y = *(__half2*)&u.y;
        __half2 A1x = hz, A1y = hz;
        int e0 = g_rowptr[i], e1 = g_rowptr[i + 1];
        int e = e0;
        for (; e + 4 <= e1; e += 4) {
            int sA = g_csrc[e], sB = g_csrc[e + 1];
            int sC = g_csrc[e + 2], sD = g_csrc[e + 3];
            uint2 vA = xsv[(long long)sA * 32 + lane];
            uint2 vB = xsv[(long long)sB * 32 + lane];
            uint2 vC = xsv[(long long)sC * 32 + lane];
            uint2 vD = xsv[(long long)sD * 32 + lane];
            A0x = __hadd2(A0x, *(__half2*)&vA.x); A0y = __hadd2(A0y, *(__half2*)&vA.y);
            A1x = __hadd2(A1x, *(__half2*)&vB.x); A1y = __hadd2(A1y, *(__half2*)&vB.y);
            A0x = __hadd2(A0x, *(__half2*)&vC.x); A0y = __hadd2(A0y, *(__half2*)&vC.y);
            A1x = __hadd2(A1x, *(__half2*)&vD.x); A1y = __hadd2(A1y, *(__half2*)&vD.y);
        }
        for (; e < e1; e++) {
            int s = g_csrc[e];
            uint2 v = xsv[(long long)s * 32 + lane];
            A0x = __hadd2(A0x, *(__half2*)&v.x);
            A0y = __hadd2(A0y, *(__half2*)&v.y);
        }
        float2 f0 = __half22float2(A0x), f1 = __half22float2(A1x);
        float2 g0 = __half22float2(A0y), g1 = __half22float2(A1y);
        float acx = f0.x + f1.x, acy = f0.y + f1.y;
        float acz = g0.x + g1.x, acw = g0.y + g1.y;
        float d = g_dis[i];
        float yx = fmaxf(fmaf(d, acx, b4.x), 0.f);
        float yy = fmaxf(fmaf(d, acy, b4.y), 0.f);
        float yz = fmaxf(fmaf(d, acz, b4.z), 0.f);
        float yw = fmaxf(fmaf(d, acw, b4.w), 0.f);
        if (!LAST) {
            uint2 o;
            *(__half2*)&o.x = __floats2half2_rn(yx, yy);
            *(__half2*)&o.y = __floats2half2_rn(yz, yw);
            ((uint2*)g_h16)[(long long)i * 32 + lane] = o;
        } else {
            int g = (int)idx_at(batch, i);
            if (g != curg) {
                if (curg >= 0) {
                    float* p = &g_pool[curg * HH + lane * 4];
                    atomicAdd(p + 0, px); atomicAdd(p + 1, py);
                    atomicAdd(p + 2, pz); atomicAdd(p + 3, pw);
                }
                curg = g; px = py = pz = pw = 0.f;
            }
            px += yx; py += yy; pz += yz; pw += yw;
        }
        s0 += yx; s1 += yy; s2 += yz; s3 += yw;
        q0 += yx * yx; q1 += yy * yy; q2 += yz * yz; q3 += yw * yw;
    }
    if (LAST && curg >= 0) {
        float* p = &g_pool[curg * HH + lane * 4];
        atomicAdd(p + 0, px); atomicAdd(p + 1, py);
        atomicAdd(p + 2, pz); atomicAdd(p + 3, pw);
    }
    __shared__ float red[2 * HH];
    red[tid] = 0.f;
    __syncthreads();
    atomicAdd(&red[lane * 4 + 0], s0);
    atomicAdd(&red[lane * 4 + 1], s1);
    atomicAdd(&red[lane * 4 + 2], s2);
    atomicAdd(&red[lane * 4 + 3], s3);
    atomicAdd(&red[HH + lane * 4 + 0], q0);
    atomicAdd(&red[HH + lane * 4 + 1], q1);
    atomicAdd(&red[HH + lane * 4 + 2], q2);
    atomicAdd(&red[HH + lane * 4 + 3], q3);
    __syncthreads();
    atomicAdd(&g_stats[tid], red[tid]);
    __threadfence();
    __syncthreads();
    __shared__ int isLast;
    if (tid == 0)
        isLast = (atomicAdd(&g_arr, 1u) == (unsigned)(AGG_BLOCKS - 1)) ? 1 : 0;
    __syncthreads();
    if (isLast) {
        if (tid < HH) {
            float m = g_stats[tid] * (1.0f / NN);
            float v = g_stats[HH + tid] * (1.0f / NN) - m * m;
            v = fmaxf(v, 0.f);
            float s = gamma[tid] * rsqrtf(v + 1e-5f);
            g_bns[tid] = s;
            g_bnt[tid] = beta[tid] - m * s;
            g_stats[tid] = 0.f;
            g_stats[HH + tid] = 0.f;
        }
        if (tid == 0) g_arr = 0u;
        if (LAST) {
            __syncthreads();
            int g = tid;
            int c = lb_batch(batch, g + 1) - lb_batch(batch, g);
            float cnt = fmaxf((float)c, 1.0f);
            float r0 = bc[0], r1 = bc[1];
#pragma unroll 4
            for (int j = 0; j < HH; j++) {
                float p = g_pool[g * HH + j] / cnt;
                p = fmaf(p, g_bns[j], g_bnt[j]);
                r0 = fmaf(p, Wc[j * KK + 0], r0);
                r1 = fmaf(p, Wc[j * KK + 1], r1);
            }
#pragma unroll
            for (int j = 0; j < CC; j++) {
                float cl = clinical[g * CC + j];
                r0 = fmaf(cl, Wc[(HH + j) * KK + 0], r0);
                r1 = fmaf(cl, Wc[(HH + j) * KK + 1], r1);
            }
            out[g * KK + 0] = r0;
            out[g * KK + 1] = r1;
        }
    }
}

// ---------------- launch ----------------
extern "C" void kernel_launch(void* const* d_in, const int* in_sizes, int n_in,
                              void* d_out, int out_size) {
    const float* x        = (const float*)d_in[0];
    const void*  ei       = d_in[1];
    const void*  batch    = d_in[2];
    const float* clinical = (const float*)d_in[3];
    const float* W1 = (const float*)d_in[4];  const float* b1 = (const float*)d_in[5];
    const float* W2 = (const float*)d_in[6];  const float* b2 = (const float*)d_in[7];
    const float* W3 = (const float*)d_in[8];  const float* b3 = (const float*)d_in[9];
    const float* g1 = (const float*)d_in[10]; const float* be1 = (const float*)d_in[11];
    const float* g2 = (const float*)d_in[12]; const float* be2 = (const float*)d_in[13];
    const float* g3 = (const float*)d_in[14]; const float* be3 = (const float*)d_in[15];
    const float* Wc = (const float*)d_in[16]; const float* bc = (const float*)d_in[17];
    float* out = (float*)d_out;

    const size_t smem0 = SMEM0_U32 * sizeof(uint32_t);   // 30 KB
    const size_t smem1 = SMEM1_U32 * sizeof(uint32_t);   // 60 KB

    cudaFuncSetAttribute(k_gemm_tc<0>,
                         cudaFuncAttributeMaxDynamicSharedMemorySize, (int)smem0);
    cudaFuncSetAttribute(k_gemm_tc<1>,
                         cudaFuncAttributeMaxDynamicSharedMemorySize, (int)smem1);

    k_init_hist<<<PRE_BLOCKS, 256>>>((const int*)ei, ei, W1);            // 1
    k_scan_place<<<PRE_BLOCKS, 256>>>(ei);                               // 2
    k_gemm_tc<0><<<GEMM_BLOCKS, 256, smem0>>>(x);                        // 3
    k_agg<false><<<AGG_BLOCKS, 256>>>(b1, batch, g1, be1,
                                      nullptr, nullptr, nullptr, nullptr); // 4 (profiled)

    k_prepw_aff_r<<<65, 256>>>(W2);                                      // 5
    k_gemm_tc<1><<<GEMM_BLOCKS, 256, smem1>>>(nullptr);                  // 6
    k_agg<false><<<AGG_BLOCKS, 256>>>(b2, batch, g2, be2,
                                      nullptr, nullptr, nullptr, nullptr); // 7

    k_prepw_aff_r<<<65, 256>>>(W3);                                      // 8
    k_gemm_tc<1><<<GEMM_BLOCKS, 256, smem1>>>(nullptr);                  // 9
    k_agg<true><<<AGG_BLOCKS, 256>>>(b3, batch, g3, be3,
                                     clinical, Wc, bc, out);             // 10
}

// round 17
// speedup vs baseline: 1.5505x; 1.0226x over previous
#include <cuda_runtime.h>
#include <cuda_fp16.h>
#include <cstdint>

#define NN 100000
#define EE 1600000
#define HH 128
#define GG 256
#define CC 16
#define KK 2

#define PRE_BLOCKS ((NN + 255) / 256)    // 391 (single wave, grid-barrier safe)
#define GEMM_BLOCKS ((NN + 127) / 128)   // 782
#define AGG_BLOCKS 888                   // 6 blocks/SM x 148 SMs = one full wave
#define AGG_WARPS (AGG_BLOCKS * 8)
#define AGG_CHUNK ((NN + AGG_WARPS - 1) / AGG_WARPS)   // 15

// ---------------- device scratch (static, allowed) ----------------
__device__ __half g_xs16[(size_t)NN * HH];
__device__ __half g_h16 [(size_t)NN * HH];
__device__ float g_dis[NN];
__device__ int   g_deg[NN];
__device__ int   g_rowptr[NN + 1];
__device__ int   g_cursor[NN];
__device__ int   g_csrc[EE];
__device__ float g_stats[2 * HH];
__device__ float g_bns[HH];
__device__ float g_bnt[HH];
__device__ float g_pool[GG * HH];
__device__ int   g_i64;
__device__ int   g_blk[PRE_BLOCKS + 8];
__device__ int   g_blkoff[PRE_BLOCKS + 8];
__device__ __half g_wh[HH * HH];           // W'^T hi fp16 [n][k]
__device__ __half g_wl[HH * HH];           // W'^T lo fp16 residual [n][k]
__device__ float g_wr[HH];
__device__ unsigned g_arr;                 // agg last-block counter
__device__ volatile unsigned g_gen;        // generation grid barrier
__device__ unsigned g_gcnt;

__device__ __forceinline__ void gsync(unsigned nblk) {
    __syncthreads();
    if (threadIdx.x == 0) {
        __threadfence();
        unsigned gen = g_gen;
        if (atomicAdd(&g_gcnt, 1u) == nblk - 1u) {
            g_gcnt = 0u;
            __threadfence();
            g_gen = gen + 1u;
        } else {
            while (g_gen == gen) __nanosleep(32);
        }
        __threadfence();
    }
    __syncthreads();
}

__device__ __forceinline__ long long idx_at(const void* p, long long i) {
    if (g_i64) return ((const long long*)p)[i];
    return (long long)((const int*)p)[i];
}

__device__ __forceinline__ void mma_f16(float* c, const uint32_t* a,
                                        uint32_t b0, uint32_t b1) {
    asm volatile(
        "mma.sync.aligned.m16n8k16.row.col.f32.f16.f16.f32 "
        "{%0,%1,%2,%3}, {%4,%5,%6,%7}, {%8,%9}, {%0,%1,%2,%3};\n"
        : "+f"(c[0]), "+f"(c[1]), "+f"(c[2]), "+f"(c[3])
        : "r"(a[0]), "r"(a[1]), "r"(a[2]), "r"(a[3]), "r"(b0), "r"(b1));
}

__device__ __forceinline__ void ldsm4(uint32_t& r0, uint32_t& r1,
                                      uint32_t& r2, uint32_t& r3, uint32_t addr) {
    asm volatile("ldmatrix.sync.aligned.m8n8.x4.shared.b16 {%0,%1,%2,%3}, [%4];"
                 : "=r"(r0), "=r"(r1), "=r"(r2), "=r"(r3) : "r"(addr));
}

__device__ __forceinline__ uint32_t pack2(float a, float b) {
    __half2 h = __floats2half2_rn(a, b);
    return *(uint32_t*)&h;
}

__device__ __forceinline__ void cpa16(uint32_t dst, const void* src, bool pred) {
    asm volatile("cp.async.cg.shared.global [%0], [%1], 16, %2;\n"
                 :: "r"(dst), "l"(src), "r"(pred ? 16 : 0));
}
__device__ __forceinline__ void cpa_commit() {
    asm volatile("cp.async.commit_group;\n");
}
template<int N>
__device__ __forceinline__ void cpa_wait() {
    asm volatile("cp.async.wait_group %0;\n" :: "n"(N));
}

// ====== launch 1: init (zero + detect + W1 prep) -> barrier -> histogram ======
__global__ void __launch_bounds__(256) k_init_hist(const int* ei32, const void* ei,
                                                   const float* __restrict__ W1) {
    int tid = threadIdx.x, b = blockIdx.x;
    int i = b * 256 + tid;
    if (b == 0 && tid < 32) {
        int lane = tid;
        int v = ei32[2 * lane + 1] | ei32[2 * (lane + 32) + 1] |
                ei32[2 * (lane + 64) + 1] | ei32[2 * (lane + 96) + 1];
        unsigned m = __ballot_sync(0xffffffffu, v != 0);
        if (lane == 0) g_i64 = (m == 0) ? 1 : 0;
    }
    if (i < NN) g_deg[i] = 0;
    if (i < GG * HH) g_pool[i] = 0.f;
    if (i < 2 * HH) g_stats[i] = 0.f;
    if (i == 0) g_arr = 0u;
    if (b == 1 && tid < HH) g_wr[tid] = 0.f;
    if (b < 64) {
        int idx = b * 256 + tid;
        int k = idx >> 7, n = idx & 127;
        float v = W1[idx];
        __half h = __float2half_rn(v);
        g_wh[n * HH + k] = h;
        g_wl[n * HH + k] = __float2half_rn(v - __half2float(h));
    }
    gsync(PRE_BLOCKS);
    for (long long e = (long long)b * 256 + tid; e < EE;
         e += (long long)PRE_BLOCKS * 256) {
        int d = (int)idx_at(ei, (long long)EE + e);
        atomicAdd(&g_deg[d], 1);
    }
}

// ====== launch 2: scan (rowptr/cursor/dis) -> barrier -> CSR place ======
__global__ void __launch_bounds__(256) k_scan_place(const void* ei) {
    int tid = threadIdx.x, b = blockIdx.x;
    int i = b * 256 + tid;
    int v = (i < NN) ? g_deg[i] : 0;
    float dis = rsqrtf((float)v + 1.0f);
    int x = v;
#pragma unroll
    for (int o = 1; o < 32; o <<= 1) {
        int y = __shfl_up_sync(0xffffffffu, x, o);
        if ((tid & 31) >= o) x += y;
    }
    __shared__ int ws[8];
    if ((tid & 31) == 31) ws[tid >> 5] = x;
    __syncthreads();
    if (tid < 8) {
        int s = ws[tid];
#pragma unroll
        for (int o = 1; o < 8; o <<= 1) {
            int y = __shfl_up_sync(0xffu, s, o);
            if (tid >= o) s += y;
        }
        ws[tid] = s;
    }
    __syncthreads();
    int warpoff = (tid >= 32) ? ws[(tid >> 5) - 1] : 0;
    if (tid == 0) g_blk[b] = ws[7];
    gsync(PRE_BLOCKS);
    if (b == 0) {
        __shared__ int s[256];
        int i0 = 2 * tid, i1 = 2 * tid + 1;
        int v0 = (i0 < PRE_BLOCKS) ? g_blk[i0] : 0;
        int v1 = (i1 < PRE_BLOCKS) ? g_blk[i1] : 0;
        int p = v0 + v1;
        s[tid] = p;
        __syncthreads();
        for (int d = 1; d < 256; d <<= 1) {
            int xx = (tid >= d) ? s[tid - d] : 0;
            __syncthreads();
            s[tid] += xx;
            __syncthreads();
        }
        int excl = s[tid] - p;
        if (i0 < PRE_BLOCKS) g_blkoff[i0] = excl;
        if (i1 < PRE_BLOCKS) g_blkoff[i1] = excl + v0;
        if (tid == 255) g_rowptr[NN] = s[255];
    }
    gsync(PRE_BLOCKS);
    int excl = x - v + warpoff + g_blkoff[b];
    if (i < NN) {
        g_rowptr[i] = excl;
        g_cursor[i] = excl;
        g_dis[i] = dis;
    }
    gsync(PRE_BLOCKS);
    for (long long e = (long long)b * 256 + tid; e < EE;
         e += (long long)PRE_BLOCKS * 256) {
        int d = (int)idx_at(ei, (long long)EE + e);
        int pos = atomicAdd(&g_cursor[d], 1);
        g_csrc[pos] = (int)idx_at(ei, e);
    }
}

__global__ void k_prepw_aff_r(const float* __restrict__ W) {
    if (blockIdx.x < 64) {
        int idx = blockIdx.x * 256 + threadIdx.x;
        int k = idx >> 7, n = idx & 127;
        float v = W[idx] * g_bns[k];
        __half h = __float2half_rn(v);
        g_wh[n * HH + k] = h;
        g_wl[n * HH + k] = __float2half_rn(v - __half2float(h));
    } else if (threadIdx.x < HH) {
        int n = threadIdx.x;
        float r = 0.f;
#pragma unroll 4
        for (int k = 0; k < HH; k++) r = fmaf(g_bnt[k], W[k * HH + n], r);
        g_wr[n] = r;
    }
}

// ---------------- fp16 tensor-core GEMM (unchanged) ----------------
#define ST 20
#define TS (128 * ST)
#define SW_H0 TS
#define SW_L0 (2 * TS)
#define SMEM0_U32 (3 * TS)          // 30 KB
#define BUFS (3 * TS)
#define SMEM1_U32 (2 * BUFS)        // 60 KB

template<int MODE>
__global__ void __launch_bounds__(256, 2) k_gemm_tc(const float* __restrict__ Ain) {
    extern __shared__ uint32_t sm[];
    int tid = threadIdx.x;
    int wid = tid >> 5, lane = tid & 31;
    int wm = wid >> 1, wn = wid & 1;
    int rbase = blockIdx.x * 128;
    uint32_t sbase = (uint32_t)__cvta_generic_to_shared((void*)sm);

    int asub = lane >> 3, ai = lane & 7;
    int a_row = (asub & 1) * 8 + ai;
    int a_k4  = (asub >> 1) * 4;
    int aoff0 = (wm * 32 + a_row) * ST + a_k4;
    int aoff1 = (wm * 32 + 16 + a_row) * ST + a_k4;
    int bsel = lane >> 4;
    int brow = lane & 7;
    int b_k4 = ((lane >> 3) & 1) * 4;
    int boff = (wn * 64 + brow) * ST + b_k4;

    float acc[2][8][4];
#pragma unroll
    for (int mt = 0; mt < 2; mt++)
#pragma unroll
        for (int j = 0; j < 8; j++)
#pragma unroll
            for (int q = 0; q < 4; q++) acc[mt][j][q] = 0.f;

    if (MODE == 0) {
        int btile = boff + (bsel ? SW_L0 : SW_H0);
        for (int ch = 0; ch < 4; ch++) {
            int kbase = ch * 32;
#pragma unroll
            for (int i = 0; i < 2; i++) {
                int idx = i * 256 + tid;
                int m = idx >> 2, q = idx & 3;
                int gr = rbase + m;
                float4 v0 = make_float4(0.f, 0.f, 0.f, 0.f);
                float4 v1 = make_float4(0.f, 0.f, 0.f, 0.f);
                if (gr < NN) {
                    v0 = *(const float4*)&Ain[(size_t)gr * HH + kbase + 8 * q];
                    v1 = *(const float4*)&Ain[(size_t)gr * HH + kbase + 8 * q + 4];
                }
                *(uint4*)&sm[m * ST + 4 * q] = make_uint4(
                    pack2(v0.x, v0.y), pack2(v0.z, v0.w),
                    pack2(v1.x, v1.y), pack2(v1.z, v1.w));
            }
#pragma unroll
            for (int i = 0; i < 2; i++) {
                int idx = i * 256 + tid;
                int n = idx >> 2, q = idx & 3;
                *(uint4*)&sm[SW_H0 + n * ST + 4 * q] =
                    *(const uint4*)&g_wh[n * HH + kbase + 8 * q];
                *(uint4*)&sm[SW_L0 + n * ST + 4 * q] =
                    *(const uint4*)&g_wl[n * HH + kbase + 8 * q];
            }
            __syncthreads();
#pragma unroll
            for (int ks = 0; ks < 2; ks++) {
                int koff = ks * 8;
                uint32_t ah[2][4];
                ldsm4(ah[0][0], ah[0][1], ah[0][2], ah[0][3],
                      sbase + 4 * (aoff0 + koff));
                ldsm4(ah[1][0], ah[1][1], ah[1][2], ah[1][3],
                      sbase + 4 * (aoff1 + koff));
#pragma unroll
                for (int j = 0; j < 8; j++) {
                    uint32_t bh0, bh1, bl0, bl1;
                    ldsm4(bh0, bh1, bl0, bl1,
                          sbase + 4 * (btile + j * 8 * ST + koff));
#pragma unroll
                    for (int mt = 0; mt < 2; mt++) {
                        mma_f16(acc[mt][j], ah[mt], bh0, bh1);
                        mma_f16(acc[mt][j], ah[mt], bl0, bl1);
                    }
                }
            }
            __syncthreads();
        }
    } else {
        int btile = boff + TS + bsel * TS;
        int m_ = tid >> 2, q_ = tid & 3;
        int m2 = (256 + tid) >> 2, q2 = (256 + tid) & 3;
#define ISSUE_CHUNK(CH, BUF) { \
        int kb = (CH) * 32; int bo = (BUF) * BUFS; \
        { int gr = rbase + m_; bool p = gr < NN; \
          const __half* s = p ? &g_h16[(size_t)gr * HH + kb + 8 * q_] : &g_h16[0]; \
          cpa16(sbase + 4 * (bo + m_ * ST + 4 * q_), s, p); } \
        { int gr = rbase + m2; bool p = gr < NN; \
          const __half* s = p ? &g_h16[(size_t)gr * HH + kb + 8 * q2] : &g_h16[0]; \
          cpa16(sbase + 4 * (bo + m2 * ST + 4 * q2), s, p); } \
        cpa16(sbase + 4 * (bo + TS + m_ * ST + 4 * q_),      &g_wh[m_ * HH + kb + 8 * q_], true); \
        cpa16(sbase + 4 * (bo + TS + m2 * ST + 4 * q2),      &g_wh[m2 * HH + kb + 8 * q2], true); \
        cpa16(sbase + 4 * (bo + 2 * TS + m_ * ST + 4 * q_),  &g_wl[m_ * HH + kb + 8 * q_], true); \
        cpa16(sbase + 4 * (bo + 2 * TS + m2 * ST + 4 * q2),  &g_wl[m2 * HH + kb + 8 * q2], true); \
        cpa_commit(); }

        ISSUE_CHUNK(0, 0);
#pragma unroll
        for (int ch = 0; ch < 4; ch++) {
            int buf = ch & 1;
            if (ch < 3) { ISSUE_CHUNK(ch + 1, buf ^ 1); cpa_wait<1>(); }
            else cpa_wait<0>();
            __syncthreads();
            int bo = buf * BUFS;
#pragma unroll
            for (int ks = 0; ks < 2; ks++) {
                int koff = ks * 8;
                uint32_t ah[2][4];
                ldsm4(ah[0][0], ah[0][1], ah[0][2], ah[0][3],
                      sbase + 4 * (bo + aoff0 + koff));
                ldsm4(ah[1][0], ah[1][1], ah[1][2], ah[1][3],
                      sbase + 4 * (bo + aoff1 + koff));
#pragma unroll
                for (int j = 0; j < 8; j++) {
                    uint32_t bh0, bh1, bl0, bl1;
                    ldsm4(bh0, bh1, bl0, bl1,
                          sbase + 4 * (bo + btile + j * 8 * ST + koff));
#pragma unroll
                    for (int mt = 0; mt < 2; mt++) {
                        mma_f16(acc[mt][j], ah[mt], bh0, bh1);
                        mma_f16(acc[mt][j], ah[mt], bl0, bl1);
                    }
                }
            }
            __syncthreads();
        }
#undef ISSUE_CHUNK
    }

    int ly = lane >> 2, lx = lane & 3;
#pragma unroll
    for (int mt = 0; mt < 2; mt++) {
        int r0 = rbase + wm * 32 + mt * 16 + ly;
        int r1 = r0 + 8;
        float d0 = (r0 < NN) ? g_dis[r0] : 0.f;
        float d1 = (r1 < NN) ? g_dis[r1] : 0.f;
#pragma unroll
        for (int j = 0; j < 8; j++) {
            int cb = wn * 64 + 8 * j + 2 * lx;
            float ra = g_wr[cb], rb = g_wr[cb + 1];
            if (r0 < NN) {
                __half2 o = __floats2half2_rn(d0 * (acc[mt][j][0] + ra),
                                              d0 * (acc[mt][j][1] + rb));
                *(__half2*)&g_xs16[(size_t)r0 * HH + cb] = o;
            }
            if (r1 < NN) {
                __half2 o = __floats2half2_rn(d1 * (acc[mt][j][2] + ra),
                                              d1 * (acc[mt][j][3] + rb));
                *(__half2*)&g_xs16[(size_t)r1 * HH + cb] = o;
            }
        }
    }
}

// --- aggregation: half2 accumulation, 32-bit addressing, int4 csrc loads ---
__device__ __forceinline__ int lb_batch(const void* batch, int val) {
    int lo = 0, hi = NN;
    while (lo < hi) {
        int mid = (lo + hi) >> 1;
        if ((int)idx_at(batch, mid) < val) lo = mid + 1;
        else hi = mid;
    }
    return lo;
}

template<bool LAST>
__global__ void __launch_bounds__(256, 6) k_agg(const float* __restrict__ bias,
                                                const void* __restrict__ batch,
                                                const float* __restrict__ gamma,
                                                const float* __restrict__ beta,
                                                const float* __restrict__ clinical,
                                                const float* __restrict__ Wc,
                                                const float* __restrict__ bc,
                                                float* __restrict__ out) {
    int tid = threadIdx.x;
    int wid = tid >> 5;
    unsigned lane = tid & 31;
    float4 b4 = ((const float4*)bias)[lane];
    float s0 = 0.f, s1 = 0.f, s2 = 0.f, s3 = 0.f;
    float q0 = 0.f, q1 = 0.f, q2 = 0.f, q3 = 0.f;
    const uint2* __restrict__ xsv = (const uint2*)g_xs16;

    int wgl = blockIdx.x * 8 + wid;
    int istart = wgl * AGG_CHUNK;
    int iend = istart + AGG_CHUNK;
    if (iend > NN) iend = NN;

    int curg = -1;
    float px = 0.f, py = 0.f, pz = 0.f, pw = 0.f;
    const __half2 hz = __floats2half2_rn(0.f, 0.f);

    for (int i = istart; i < iend; i++) {
        uint2 u = xsv[(unsigned)i * 32u + lane];      // self term
        __half2 A0x = *(__half2*)&u.x, A0y = *(__half2*)&u.y;
        __half2 A1x = hz, A1y = hz;
        int e0 = g_rowptr[i], e1 = g_rowptr[i + 1];
        int e = e0;
        // peel to 16B alignment of csrc
        for (; e < e1 && (e & 3); e++) {
            unsigned s = (unsigned)g_csrc[e];
            uint2 v = xsv[s * 32u + lane];
            A0x = __hadd2(A0x, *(__half2*)&v.x);
            A0y = __hadd2(A0y, *(__half2*)&v.y);
        }
        for (; e + 4 <= e1; e += 4) {
            int4 ss = *(const int4*)&g_csrc[e];
            uint2 vA = xsv[(unsigned)ss.x * 32u + lane];
            uint2 vB = xsv[(unsigned)ss.y * 32u + lane];
            uint2 vC = xsv[(unsigned)ss.z * 32u + lane];
            uint2 vD = xsv[(unsigned)ss.w * 32u + lane];
            A0x = __hadd2(A0x, *(__half2*)&vA.x); A0y = __hadd2(A0y, *(__half2*)&vA.y);
            A1x = __hadd2(A1x, *(__half2*)&vB.x); A1y = __hadd2(A1y, *(__half2*)&vB.y);
            A0x = __hadd2(A0x, *(__half2*)&vC.x); A0y = __hadd2(A0y, *(__half2*)&vC.y);
            A1x = __hadd2(A1x, *(__half2*)&vD.x); A1y = __hadd2(A1y, *(__half2*)&vD.y);
        }
        for (; e < e1; e++) {
            unsigned s = (unsigned)g_csrc[e];
            uint2 v = xsv[s * 32u + lane];
            A0x = __hadd2(A0x, *(__half2*)&v.x);
            A0y = __hadd2(A0y, *(__half2*)&v.y);
        }
        float2 f0 = __half22float2(A0x), f1 = __half22float2(A1x);
        float2 g0 = __half22float2(A0y), g1 = __half22float2(A1y);
        float acx = f0.x + f1.x, acy = f0.y + f1.y;
        float acz = g0.x + g1.x, acw = g0.y + g1.y;
        float d = g_dis[i];
        float yx = fmaxf(fmaf(d, acx, b4.x), 0.f);
        float yy = fmaxf(fmaf(d, acy, b4.y), 0.f);
        float yz = fmaxf(fmaf(d, acz, b4.z), 0.f);
        float yw = fmaxf(fmaf(d, acw, b4.w), 0.f);
        if (!LAST) {
            uint2 o;
            *(__half2*)&o.x = __floats2half2_rn(yx, yy);
            *(__half2*)&o.y = __floats2half2_rn(yz, yw);
            ((uint2*)g_h16)[(unsigned)i * 32u + lane] = o;
        } else {
            int g = (int)idx_at(batch, i);
            if (g != curg) {
                if (curg >= 0) {
                    float* p = &g_pool[curg * HH + lane * 4];
                    atomicAdd(p + 0, px); atomicAdd(p + 1, py);
                    atomicAdd(p + 2, pz); atomicAdd(p + 3, pw);
                }
                curg = g; px = py = pz = pw = 0.f;
            }
            px += yx; py += yy; pz += yz; pw += yw;
        }
        s0 += yx; s1 += yy; s2 += yz; s3 += yw;
        q0 += yx * yx; q1 += yy * yy; q2 += yz * yz; q3 += yw * yw;
    }
    if (LAST && curg >= 0) {
        float* p = &g_pool[curg * HH + lane * 4];
        atomicAdd(p + 0, px); atomicAdd(p + 1, py);
        atomicAdd(p + 2, pz); atomicAdd(p + 3, pw);
    }
    __shared__ float red[2 * HH];
    red[tid] = 0.f;
    __syncthreads();
    atomicAdd(&red[lane * 4 + 0], s0);
    atomicAdd(&red[lane * 4 + 1], s1);
    atomicAdd(&red[lane * 4 + 2], s2);
    atomicAdd(&red[lane * 4 + 3], s3);
    atomicAdd(&red[HH + lane * 4 + 0], q0);
    atomicAdd(&red[HH + lane * 4 + 1], q1);
    atomicAdd(&red[HH + lane * 4 + 2], q2);
    atomicAdd(&red[HH + lane * 4 + 3], q3);
    __syncthreads();
    atomicAdd(&g_stats[tid], red[tid]);
    __threadfence();
    __syncthreads();
    __shared__ int isLast;
    if (tid == 0)
        isLast = (atomicAdd(&g_arr, 1u) == (unsigned)(AGG_BLOCKS - 1)) ? 1 : 0;
    __syncthreads();
    if (isLast) {
        if (tid < HH) {
            float m = g_stats[tid] * (1.0f / NN);
            float v = g_stats[HH + tid] * (1.0f / NN) - m * m;
            v = fmaxf(v, 0.f);
            float s = gamma[tid] * rsqrtf(v + 1e-5f);
            g_bns[tid] = s;
            g_bnt[tid] = beta[tid] - m * s;
            g_stats[tid] = 0.f;
            g_stats[HH + tid] = 0.f;
        }
        if (tid == 0) g_arr = 0u;
        if (LAST) {
            __syncthreads();
            int g = tid;
            int c = lb_batch(batch, g + 1) - lb_batch(batch, g);
            float cnt = fmaxf((float)c, 1.0f);
            float r0 = bc[0], r1 = bc[1];
#pragma unroll 4
            for (int j = 0; j < HH; j++) {
                float p = g_pool[g * HH + j] / cnt;
                p = fmaf(p, g_bns[j], g_bnt[j]);
                r0 = fmaf(p, Wc[j * KK + 0], r0);
                r1 = fmaf(p, Wc[j * KK + 1], r1);
            }
#pragma unroll
            for (int j = 0; j < CC; j++) {
                float cl = clinical[g * CC + j];
                r0 = fmaf(cl, Wc[(HH + j) * KK + 0], r0);
                r1 = fmaf(cl, Wc[(HH + j) * KK + 1], r1);
            }
            out[g * KK + 0] = r0;
            out[g * KK + 1] = r1;
        }
    }
}

// ---------------- launch ----------------
extern "C" void kernel_launch(void* const* d_in, const int* in_sizes, int n_in,
                              void* d_out, int out_size) {
    const float* x        = (const float*)d_in[0];
    const void*  ei       = d_in[1];
    const void*  batch    = d_in[2];
    const float* clinical = (const float*)d_in[3];
    const float* W1 = (const float*)d_in[4];  const float* b1 = (const float*)d_in[5];
    const float* W2 = (const float*)d_in[6];  const float* b2 = (const float*)d_in[7];
    const float* W3 = (const float*)d_in[8];  const float* b3 = (const float*)d_in[9];
    const float* g1 = (const float*)d_in[10]; const float* be1 = (const float*)d_in[11];
    const float* g2 = (const float*)d_in[12]; const float* be2 = (const float*)d_in[13];
    const float* g3 = (const float*)d_in[14]; const float* be3 = (const float*)d_in[15];
    const float* Wc = (const float*)d_in[16]; const float* bc = (const float*)d_in[17];
    float* out = (float*)d_out;

    const size_t smem0 = SMEM0_U32 * sizeof(uint32_t);   // 30 KB
    const size_t smem1 = SMEM1_U32 * sizeof(uint32_t);   // 60 KB

    cudaFuncSetAttribute(k_gemm_tc<0>,
                         cudaFuncAttributeMaxDynamicSharedMemorySize, (int)smem0);
    cudaFuncSetAttribute(k_gemm_tc<1>,
                         cudaFuncAttributeMaxDynamicSharedMemorySize, (int)smem1);

    k_init_hist<<<PRE_BLOCKS, 256>>>((const int*)ei, ei, W1);            // 1
    k_scan_place<<<PRE_BLOCKS, 256>>>(ei);                               // 2
    k_gemm_tc<0><<<GEMM_BLOCKS, 256, smem0>>>(x);                        // 3
    k_agg<false><<<AGG_BLOCKS, 256>>>(b1, batch, g1, be1,
                                      nullptr, nullptr, nullptr, nullptr); // 4 (profiled)

    k_prepw_aff_r<<<65, 256>>>(W2);                                      // 5
    k_gemm_tc<1><<<GEMM_BLOCKS, 256, smem1>>>(nullptr);                  // 6
    k_agg<false><<<AGG_BLOCKS, 256>>>(b2, batch, g2, be2,
                                      nullptr, nullptr, nullptr, nullptr); // 7

    k_prepw_aff_r<<<65, 256>>>(W3);                                      // 8
    k_gemm_tc<1><<<GEMM_BLOCKS, 256, smem1>>>(nullptr);                  // 9
    k_agg<true><<<AGG_BLOCKS, 256>>>(b3, batch, g3, be3,
                                     clinical, Wc, bc, out);             // 10
}